// round 14
// baseline (speedup 1.0000x reference)
#include <cuda_runtime.h>
#include <cuda_fp16.h>

#define TC 8192
#define TF 65536
#define D_MAX 36.0f
#define NGAUSS 300

__device__ __align__(16) uint2  g_tabn[TF * 32];        // fine fp16 nearest table (16 MB)
__device__ __align__(16) float  g_x[4096 * 128];
__device__ __align__(16) float  g_fA[4096 * 128];
__device__ __align__(16) float  g_fB[4096 * 128];
__device__ __align__(16) float  g_ysum[4096 * 128];
__device__ __align__(16) float  g_fbias[128];
__device__ __align__(16) unsigned short g_idx[32 * 128 * 128];  // table indices (1 MB)
__device__ __align__(16) __half g_wf2T_h[128 * 128];    // w_f2out^T hi/lo fp16 [n][k]
__device__ __align__(16) __half g_wf2T_l[128 * 128];
__device__ __align__(16) __half g_comboT_h[128 * 128];  // (w_out@w_in2f)^T hi/lo
__device__ __align__(16) __half g_comboT_l[128 * 128];
__device__ __align__(16) __half g_woutT_h[128 * 128];   // w_out^T hi/lo
__device__ __align__(16) __half g_woutT_l[128 * 128];
__device__ __align__(16) __half g_aw1T_h[128 * 128];    // w_aw1^T hi/lo
__device__ __align__(16) __half g_aw1T_l[128 * 128];

__device__ __forceinline__ float sspf(float x) {
    return fmaxf(x, 0.0f) + log1pf(__expf(-fabsf(x))) - 0.69314718055994531f;
}

__device__ __forceinline__ void mma16816(float& d0, float& d1, float& d2, float& d3,
                                         unsigned a0, unsigned a1, unsigned a2, unsigned a3,
                                         unsigned b0, unsigned b1)
{
    asm volatile(
        "mma.sync.aligned.m16n8k16.row.col.f32.f16.f16.f32 "
        "{%0,%1,%2,%3}, {%4,%5,%6,%7}, {%8,%9}, {%0,%1,%2,%3};\n"
        : "+f"(d0), "+f"(d1), "+f"(d2), "+f"(d3)
        : "r"(a0), "r"(a1), "r"(a2), "r"(a3), "r"(b0), "r"(b1));
}

#define YHS 136
#define IDXU 68   // idx smem row stride in uints (136 ushorts, bank-staggered)
__device__ __forceinline__ void split_gemm(float& d0, float& d1, float& d2, float& d3,
                                           const __half* Ah, const __half* Al,
                                           const __half* BTh, const __half* BTl,
                                           int gr, int ct, int nc)
{
#pragma unroll
    for (int ks = 0; ks < 8; ks++) {
        int kb = ks * 16 + ct * 2;
        unsigned a0 = *reinterpret_cast<const unsigned*>(Ah + gr * YHS + kb);
        unsigned a1 = *reinterpret_cast<const unsigned*>(Ah + (gr + 8) * YHS + kb);
        unsigned a2 = *reinterpret_cast<const unsigned*>(Ah + gr * YHS + kb + 8);
        unsigned a3 = *reinterpret_cast<const unsigned*>(Ah + (gr + 8) * YHS + kb + 8);
        unsigned l0 = *reinterpret_cast<const unsigned*>(Al + gr * YHS + kb);
        unsigned l1 = *reinterpret_cast<const unsigned*>(Al + (gr + 8) * YHS + kb);
        unsigned l2 = *reinterpret_cast<const unsigned*>(Al + gr * YHS + kb + 8);
        unsigned l3 = *reinterpret_cast<const unsigned*>(Al + (gr + 8) * YHS + kb + 8);
        unsigned b0 = *reinterpret_cast<const unsigned*>(BTh + nc * 128 + kb);
        unsigned b1 = *reinterpret_cast<const unsigned*>(BTh + nc * 128 + kb + 8);
        unsigned c0 = *reinterpret_cast<const unsigned*>(BTl + nc * 128 + kb);
        unsigned c1 = *reinterpret_cast<const unsigned*>(BTl + nc * 128 + kb + 8);
        mma16816(d0, d1, d2, d3, a0, a1, a2, a3, b0, b1);
        mma16816(d0, d1, d2, d3, l0, l1, l2, l3, b0, b1);
        mma16816(d0, d1, d2, d3, a0, a1, a2, a3, c0, c1);
    }
}

__device__ __forceinline__ void hilo_store(__half* H, __half* L, int row, int col,
                                           float v0, float v1)
{
    __half2 h = __floats2half2_rn(v0, v1);
    float2 q = __half22float2(h);
    __half2 l = __floats2half2_rn(v0 - q.x, v1 - q.y);
    *reinterpret_cast<unsigned*>(H + row * YHS + col) = *reinterpret_cast<unsigned*>(&h);
    *reinterpret_cast<unsigned*>(L + row * YHS + col) = *reinterpret_cast<unsigned*>(&l);
}

// ---- fused coarse+fine table: 512 blocks x 256 thr ----
__global__ void k_tab(const float* __restrict__ w1, const float* __restrict__ b1,
                      const float* __restrict__ w2, const float* __restrict__ b2)
{
    __shared__ float w1s[32 * 128];
    __shared__ float rbf_s[17 * 32];
    __shared__ float As[17 * 128];
    const float hc = D_MAX / (float)TC;
    const float dc = 30.0f / 299.0f;
    const int t0c = blockIdx.x * 16, tid = threadIdx.x;
    const int tg = tid >> 7, h = tid & 127, T0 = tg * 8;

    float dmin = (float)t0c * hc, dmax = (float)(t0c + 16) * hc;
    int glo = (int)floorf((dmin - 1.4f) / dc); if (glo < 0) glo = 0;
    int ghi = (int)ceilf((dmax + 1.4f) / dc);  if (ghi > NGAUSS - 1) ghi = NGAUSS - 1;
    int ng = ghi - glo + 1; if (ng < 0) ng = 0; if (ng > 32) ng = 32;

    for (int idx = tid; idx < ng * 128; idx += 256) w1s[idx] = w1[glo * 128 + idx];
    for (int idx = tid; idx < 17 * ng; idx += 256) {
        int t = idx / ng, g = idx % ng;
        int tc = min(t0c + t, TC - 1);
        float u = (float)tc * hc - (float)(glo + g) * dc;
        rbf_s[t * 32 + g] = __expf(-10.0f * u * u);
    }
    __syncthreads();

    float acc[9];
#pragma unroll
    for (int t = 0; t < 9; t++) acc[t] = 0.0f;
    for (int g = 0; g < ng; g++) {
        float w = w1s[g * 128 + h];
#pragma unroll
        for (int t = 0; t < 9; t++) acc[t] += rbf_s[(T0 + t) * 32 + g] * w;
    }
    float bb = b1[h];
#pragma unroll
    for (int t = 0; t < 9; t++)
        if (tg == 0 || t > 0) As[(T0 + t) * 128 + h] = sspf(acc[t] + bb);
    __syncthreads();

#pragma unroll
    for (int t = 0; t < 9; t++) acc[t] = 0.0f;
    for (int k = 0; k < 128; k++) {
        float w = __ldg(&w2[k * 128 + h]);
#pragma unroll
        for (int t = 0; t < 9; t++) acc[t] += As[(T0 + t) * 128 + k] * w;
    }
    float b2v = b2[h];
    __syncthreads();
#pragma unroll
    for (int t = 0; t < 9; t++)
        if (tg == 0 || t > 0) As[(T0 + t) * 128 + h] = acc[t] + b2v;
    __syncthreads();

    for (int task = tid; task < 4096; task += 256) {
        int rho = task >> 5, h4 = task & 31;
        int u = rho >> 3;
        float fr = (float)(rho & 7) * 0.125f;
        float4 a = *reinterpret_cast<const float4*>(As + u * 128 + h4 * 4);
        float4 b = *reinterpret_cast<const float4*>(As + (u + 1) * 128 + h4 * 4);
        __half2 h01 = __floats2half2_rn(a.x + fr * (b.x - a.x), a.y + fr * (b.y - a.y));
        __half2 h23 = __floats2half2_rn(a.z + fr * (b.z - a.z), a.w + fr * (b.w - a.w));
        uint2 o;
        o.x = *reinterpret_cast<unsigned*>(&h01);
        o.y = *reinterpret_cast<unsigned*>(&h23);
        g_tabn[(blockIdx.x * 128 + rho) * 32 + h4] = o;
    }
}

// ---- fused setup (roles unchanged from R12) ----
__global__ void k_setup(const int* __restrict__ z, const float* __restrict__ emb,
                        const float* __restrict__ w_in2f, const float* __restrict__ w_out,
                        const float* __restrict__ b_out, const float* __restrict__ w_f2out,
                        const float* __restrict__ w_aw1, const float* __restrict__ r)
{
    extern __shared__ float sm[];
    float* ws = sm;            // [128][128]
    float* xs = sm + 16384;    // [16][128]
    const int bx = blockIdx.x, tid = threadIdx.x;

    if (bx >= 277) {           // distance -> table index, one block per batch
        float* rs = sm;
        const int b = bx - 277;
        if (tid < 128) {
            const float* rp = r + (b * 128 + tid) * 3;
            rs[tid] = rp[0]; rs[128 + tid] = rp[1]; rs[256 + tid] = rp[2];
        }
        __syncthreads();
        const float inv_h = (float)TF / D_MAX;
        for (int task = tid; task < 16384; task += 256) {
            int i = task >> 7, j = task & 127;
            float dx = rs[i] - rs[j], dy = rs[128 + i] - rs[128 + j], dz = rs[256 + i] - rs[256 + j];
            float d = sqrtf(dx * dx + dy * dy + dz * dz + 1e-12f);
            g_idx[b * 16384 + task] =
                (unsigned short)fminf(d * inv_h + 0.5f, (float)(TF - 1));
        }
        return;
    }
    if (bx >= 265) {
        const float* src; __half *dh, *dl;
        int role = (bx - 265) >> 2, base = ((bx - 265) & 3) * 4096;
        if (role == 0)      { src = w_f2out; dh = g_wf2T_h;  dl = g_wf2T_l; }
        else if (role == 1) { src = w_out;   dh = g_woutT_h; dl = g_woutT_l; }
        else                { src = w_aw1;   dh = g_aw1T_h;  dl = g_aw1T_l; }
        for (int e = base + tid; e < base + 4096; e += 256) {
            int n = e >> 7, k = e & 127;
            float v = src[k * 128 + n];
            __half hh = __float2half_rn(v);
            dh[e] = hh;
            dl[e] = __float2half_rn(v - __half2float(hh));
        }
        return;
    }

    for (int idx = tid; idx < 16384; idx += 256) ws[idx] = w_in2f[idx];
    if (bx < 256) {
        int r0 = bx * 16;
        for (int idx = tid; idx < 2048; idx += 256) {
            int i = idx >> 7, h = idx & 127;
            int zi = z[r0 + i];
            float v = emb[zi * 128 + h];
            xs[idx] = v;
            g_x[r0 * 128 + idx] = v;
            g_ysum[r0 * 128 + idx] = 0.0f;
        }
    } else if (bx < 264) {
        int r0 = (bx - 256) * 16;
        for (int idx = tid; idx < 2048; idx += 256) xs[idx] = w_out[r0 * 128 + idx];
    }
    __syncthreads();

    if (bx == 264) {
        if (tid < 128) {
            float s = 0.0f;
            for (int m = 0; m < 128; m++) s += __ldg(&b_out[m]) * ws[m * 128 + tid];
            g_fbias[tid] = s;
        }
        return;
    }
    const int rg = tid >> 5, hg = tid & 31;
    float a[2][4];
#pragma unroll
    for (int rr = 0; rr < 2; rr++)
#pragma unroll
        for (int c = 0; c < 4; c++) a[rr][c] = 0.0f;
    for (int k = 0; k < 128; k++) {
        float4 wb = *reinterpret_cast<const float4*>(ws + k * 128 + hg * 4);
        float y0 = xs[(rg * 2) * 128 + k], y1 = xs[(rg * 2 + 1) * 128 + k];
        a[0][0] += y0 * wb.x; a[0][1] += y0 * wb.y; a[0][2] += y0 * wb.z; a[0][3] += y0 * wb.w;
        a[1][0] += y1 * wb.x; a[1][1] += y1 * wb.y; a[1][2] += y1 * wb.z; a[1][3] += y1 * wb.w;
    }
    if (bx < 256) {
#pragma unroll
        for (int rr = 0; rr < 2; rr++)
            *reinterpret_cast<float4*>(g_fA + (bx * 16 + rg * 2 + rr) * 128 + hg * 4) =
                make_float4(a[rr][0], a[rr][1], a[rr][2], a[rr][3]);
    } else {
        __syncthreads();
#pragma unroll
        for (int rr = 0; rr < 2; rr++)
#pragma unroll
            for (int c = 0; c < 4; c++)
                xs[(rg * 2 + rr) * 128 + hg * 4 + c] = a[rr][c];
        __syncthreads();
        int r0 = (bx - 256) * 16;
        for (int e = tid; e < 2048; e += 256) {
            int n = e >> 4, q = e & 15;
            float v = xs[q * 128 + n];
            __half hh = __float2half_rn(v);
            g_comboT_h[n * 128 + r0 + q] = hh;
            g_comboT_l[n * 128 + r0 + q] = __float2half_rn(v - __half2float(hh));
        }
    }
}

// ---- fused iteration: broadcast-gather + split-mma epilogue / readout ----
__global__ void __launch_bounds__(512, 2)
k_iter(const float* __restrict__ b_f2out, const float* __restrict__ b_out,
       const float* __restrict__ b_aw1, const float* __restrict__ w_aw2,
       const float* __restrict__ b_aw2, float* __restrict__ out, int mode)
{
    extern __shared__ char smb[];
    float*          f_s   = (float*)smb;                    // 65536 [j][h] fp32
    __half*         yh    = (__half*)(smb + 65536);         // 4352 each
    __half*         yl    = (__half*)(smb + 69888);
    __half*         y2h   = (__half*)(smb + 74240);
    __half*         y2l   = (__half*)(smb + 78592);
    unsigned*       idx_s = (unsigned*)(smb + 82944);       // 16 rows x 68 uints = 4352 B
    float*          bias1 = (float*)(smb + 87296);          // 128
    float*          fb_s  = (float*)(smb + 87808);          // 128 (fbias | b_out)
    float*          baw1  = (float*)(smb + 88320);          // 128
    float*          w2ro  = (float*)(smb + 88832);          // 128
    float*          red   = (float*)(smb + 89344);          // 16
    const int it = blockIdx.x, b = blockIdx.y, tid = threadIdx.x;
    const int flag = (mode == 1) ? 1 : 0;
    const float*  f_in  = flag ? g_fB : g_fA;
    float*        f_out = flag ? g_fA : g_fB;

    if (tid < 128) bias1[tid] = b_f2out[tid];
    else if (tid < 256) fb_s[tid - 128] = (mode == 2) ? b_out[tid - 128] : g_fbias[tid - 128];
    else if (tid < 384) baw1[tid - 256] = b_aw1[tid - 256];
    else w2ro[tid - 384] = w_aw2[tid - 384];
    if (tid < 16) red[tid] = 0.0f;
    {
        // stage idx: 16 rows x 64 uints, bank-staggered stride IDXU
        const unsigned* gi = reinterpret_cast<const unsigned*>(g_idx + (b * 128 + it * 16) * 128);
        int e0 = tid, e1 = tid + 512;
        idx_s[(e0 >> 6) * IDXU + (e0 & 63)] = gi[e0];
        idx_s[(e1 >> 6) * IDXU + (e1 & 63)] = gi[e1];
    }
    {
        const uint4* src = reinterpret_cast<const uint4*>(f_in + b * 16384);
        uint4* dst = reinterpret_cast<uint4*>(f_s);
        for (int i2 = tid; i2 < 4096; i2 += 512) dst[i2] = src[i2];
    }
    __syncthreads();

    const int w = tid >> 5, lane = tid & 31;
    // gather mapping: warp = (row-group w>>2, h-quarter w&3); lane = (rl lane>>3, hh lane&7)
    {
        const int row = (w >> 2) * 4 + (lane >> 3);
        const int h4 = (w & 3) * 8 + (lane & 7);
        const unsigned* ip = idx_s + row * IDXU;
        float a0 = 0.f, a1 = 0.f, a2 = 0.f, a3 = 0.f;
#pragma unroll 8
        for (int j2 = 0; j2 < 64; j2++) {
            unsigned pr = ip[j2];
            unsigned t0 = pr & 0xFFFFu, t1 = pr >> 16;
            uint2 u0 = g_tabn[t0 * 32 + h4];
            uint2 u1 = g_tabn[t1 * 32 + h4];
            float4 fv0 = *reinterpret_cast<const float4*>(f_s + (j2 * 2) * 128 + h4 * 4);
            float4 fv1 = *reinterpret_cast<const float4*>(f_s + (j2 * 2 + 1) * 128 + h4 * 4);
            {
                __half2 w01 = *reinterpret_cast<__half2*>(&u0.x);
                __half2 w23 = *reinterpret_cast<__half2*>(&u0.y);
                float2 pw0 = __half22float2(w01), pw1 = __half22float2(w23);
                a0 = fmaf(pw0.x, fv0.x, a0);
                a1 = fmaf(pw0.y, fv0.y, a1);
                a2 = fmaf(pw1.x, fv0.z, a2);
                a3 = fmaf(pw1.y, fv0.w, a3);
            }
            {
                __half2 w01 = *reinterpret_cast<__half2*>(&u1.x);
                __half2 w23 = *reinterpret_cast<__half2*>(&u1.y);
                float2 pw0 = __half22float2(w01), pw1 = __half22float2(w23);
                a0 = fmaf(pw0.x, fv1.x, a0);
                a1 = fmaf(pw0.y, fv1.y, a1);
                a2 = fmaf(pw1.x, fv1.z, a2);
                a3 = fmaf(pw1.y, fv1.w, a3);
            }
        }
        hilo_store(yh, yl, row, h4 * 4, a0, a1);
        hilo_store(yh, yl, row, h4 * 4 + 2, a2, a3);
    }
    __syncthreads();

    // ---- GEMM1: y2 = ssp(y @ w_f2out + b); ysum accumulate ----
    const int gr = lane >> 2, ct = lane & 3, n0 = w * 8;
    const int nc = n0 + gr;
    const int c0 = n0 + ct * 2;
    const int row0 = gr, row1 = gr + 8;
    float d0 = 0.f, d1 = 0.f, d2 = 0.f, d3 = 0.f;
    split_gemm(d0, d1, d2, d3, yh, yl, g_wf2T_h, g_wf2T_l, gr, ct, nc);
    float s0, s1, s2, s3;
    {
        float v0 = sspf(d0 + bias1[c0]), v1 = sspf(d1 + bias1[c0 + 1]);
        float v2 = sspf(d2 + bias1[c0]), v3 = sspf(d3 + bias1[c0 + 1]);
        int gr0 = (b * 128 + it * 16 + row0) * 128 + c0;
        int gr1 = (b * 128 + it * 16 + row1) * 128 + c0;
        float2 t0 = *reinterpret_cast<float2*>(g_ysum + gr0);
        float2 t1 = *reinterpret_cast<float2*>(g_ysum + gr1);
        s0 = t0.x + v0; s1 = t0.y + v1; s2 = t1.x + v2; s3 = t1.y + v3;
        __syncthreads();            // yh/yl reads done before overwrite below
        if (mode != 2) {
            *reinterpret_cast<float2*>(g_ysum + gr0) = make_float2(s0, s1);
            *reinterpret_cast<float2*>(g_ysum + gr1) = make_float2(s2, s3);
            hilo_store(y2h, y2l, row0, c0, v0, v1);
            hilo_store(y2h, y2l, row1, c0, v2, v3);
        } else {
            hilo_store(y2h, y2l, row0, c0, s0, s1);   // A = final ysum
            hilo_store(y2h, y2l, row1, c0, s2, s3);
        }
    }
    __syncthreads();

    if (mode != 2) {
        // ---- GEMM2: f_out = f_in + fbias + y2 @ combo ----
        d0 = d1 = d2 = d3 = 0.f;
        split_gemm(d0, d1, d2, d3, y2h, y2l, g_comboT_h, g_comboT_l, gr, ct, nc);
        int gr0 = (b * 128 + it * 16 + row0) * 128 + c0;
        int gr1 = (b * 128 + it * 16 + row1) * 128 + c0;
        float2 fi0 = *reinterpret_cast<const float2*>(f_in + gr0);
        float2 fi1 = *reinterpret_cast<const float2*>(f_in + gr1);
        float fb0 = fb_s[c0], fb1 = fb_s[c0 + 1];
        *reinterpret_cast<float2*>(f_out + gr0) = make_float2(fi0.x + fb0 + d0, fi0.y + fb1 + d1);
        *reinterpret_cast<float2*>(f_out + gr1) = make_float2(fi1.x + fb0 + d2, fi1.y + fb1 + d3);
        return;
    }

    // ---- mode 2: readout ----
    d0 = d1 = d2 = d3 = 0.f;
    split_gemm(d0, d1, d2, d3, y2h, y2l, g_woutT_h, g_woutT_l, gr, ct, nc);
    {
        int gr0 = (b * 128 + it * 16 + row0) * 128 + c0;
        int gr1 = (b * 128 + it * 16 + row1) * 128 + c0;
        float2 x0a = *reinterpret_cast<const float2*>(g_x + gr0);
        float2 x0b = *reinterpret_cast<const float2*>(g_x + gr1);
        float bo0 = 3.0f * fb_s[c0], bo1 = 3.0f * fb_s[c0 + 1];
        hilo_store(yh, yl, row0, c0, x0a.x + d0 + bo0, x0a.y + d1 + bo1);
        hilo_store(yh, yl, row1, c0, x0b.x + d2 + bo0, x0b.y + d3 + bo1);
    }
    __syncthreads();

    d0 = d1 = d2 = d3 = 0.f;
    split_gemm(d0, d1, d2, d3, yh, yl, g_aw1T_h, g_aw1T_l, gr, ct, nc);
    {
        float t0 = sspf(d0 + baw1[c0]), t1 = sspf(d1 + baw1[c0 + 1]);
        float t2 = sspf(d2 + baw1[c0]), t3 = sspf(d3 + baw1[c0 + 1]);
        float w0 = w2ro[c0], w1 = w2ro[c0 + 1];
        atomicAdd(&red[row0], t0 * w0 + t1 * w1);
        atomicAdd(&red[row1], t2 * w0 + t3 * w1);
    }
    __syncthreads();
    if (tid < 16)
        out[b * 128 + it * 16 + tid] = red[tid] + b_aw2[0];
}

extern "C" void kernel_launch(void* const* d_in, const int* in_sizes, int n_in,
                              void* d_out, int out_size)
{
    const int*   z       = (const int*)  d_in[0];
    const float* r       = (const float*)d_in[1];
    const float* emb     = (const float*)d_in[2];
    const float* w_in2f  = (const float*)d_in[3];
    const float* w_f1    = (const float*)d_in[4];
    const float* b_f1    = (const float*)d_in[5];
    const float* w_f2    = (const float*)d_in[6];
    const float* b_f2    = (const float*)d_in[7];
    const float* w_f2out = (const float*)d_in[8];
    const float* b_f2out = (const float*)d_in[9];
    const float* w_out   = (const float*)d_in[10];
    const float* b_out   = (const float*)d_in[11];
    const float* w_aw1   = (const float*)d_in[12];
    const float* b_aw1   = (const float*)d_in[13];
    const float* w_aw2   = (const float*)d_in[14];
    const float* b_aw2   = (const float*)d_in[15];
    float* out = (float*)d_out;

    cudaFuncSetAttribute(k_setup, cudaFuncAttributeMaxDynamicSharedMemorySize, 73728);
    cudaFuncSetAttribute(k_iter,  cudaFuncAttributeMaxDynamicSharedMemorySize, 89472);

    k_tab<<<512, 256>>>(w_f1, b_f1, w_f2, b_f2);
    k_setup<<<309, 256, 73728>>>(z, emb, w_in2f, w_out, b_out, w_f2out, w_aw1, r);
    for (int it = 0; it < 3; it++)
        k_iter<<<dim3(8, 32), 512, 89472>>>(b_f2out, b_out, b_aw1, w_aw2, b_aw2, out, it);
}

// round 15
// speedup vs baseline: 1.0365x; 1.0365x over previous
#include <cuda_runtime.h>
#include <cuda_fp16.h>

#define TC 8192
#define TF 65536
#define D_MAX 36.0f
#define NGAUSS 300

__device__ __align__(16) uint2  g_tabn[TF * 32];        // fine fp16 nearest table (16 MB)
__device__ __align__(16) float  g_x[4096 * 128];
__device__ __align__(16) float  g_fA[4096 * 128];
__device__ __align__(16) float  g_fB[4096 * 128];
__device__ __align__(16) __half g_fhA[4096 * 128];      // fp16 f mirrors for gather
__device__ __align__(16) __half g_fhB[4096 * 128];
__device__ __align__(16) float  g_y[4096 * 128];
__device__ __align__(16) float  g_ysum[4096 * 128];
__device__ __align__(16) float  g_fbias[128];
__device__ __align__(16) unsigned short g_idx[32 * 128 * 128];  // table indices (1 MB)
__device__ __align__(16) __half g_wf2T_h[128 * 128];    // w_f2out^T hi/lo fp16 [n][k]
__device__ __align__(16) __half g_wf2T_l[128 * 128];
__device__ __align__(16) __half g_comboT_h[128 * 128];  // (w_out@w_in2f)^T hi/lo
__device__ __align__(16) __half g_comboT_l[128 * 128];
__device__ __align__(16) __half g_woutT_h[128 * 128];   // w_out^T hi/lo
__device__ __align__(16) __half g_woutT_l[128 * 128];
__device__ __align__(16) __half g_aw1T_h[128 * 128];    // w_aw1^T hi/lo
__device__ __align__(16) __half g_aw1T_l[128 * 128];

__device__ __forceinline__ float sspf(float x) {
    return fmaxf(x, 0.0f) + log1pf(__expf(-fabsf(x))) - 0.69314718055994531f;
}

__device__ __forceinline__ void mma16816(float& d0, float& d1, float& d2, float& d3,
                                         unsigned a0, unsigned a1, unsigned a2, unsigned a3,
                                         unsigned b0, unsigned b1)
{
    asm volatile(
        "mma.sync.aligned.m16n8k16.row.col.f32.f16.f16.f32 "
        "{%0,%1,%2,%3}, {%4,%5,%6,%7}, {%8,%9}, {%0,%1,%2,%3};\n"
        : "+f"(d0), "+f"(d1), "+f"(d2), "+f"(d3)
        : "r"(a0), "r"(a1), "r"(a2), "r"(a3), "r"(b0), "r"(b1));
}

#define YHS 136
__device__ __forceinline__ void split_gemm(float& d0, float& d1, float& d2, float& d3,
                                           const __half* Ah, const __half* Al,
                                           const __half* BTh, const __half* BTl,
                                           int gr, int ct, int nc)
{
#pragma unroll
    for (int ks = 0; ks < 8; ks++) {
        int kb = ks * 16 + ct * 2;
        unsigned a0 = *reinterpret_cast<const unsigned*>(Ah + gr * YHS + kb);
        unsigned a1 = *reinterpret_cast<const unsigned*>(Ah + (gr + 8) * YHS + kb);
        unsigned a2 = *reinterpret_cast<const unsigned*>(Ah + gr * YHS + kb + 8);
        unsigned a3 = *reinterpret_cast<const unsigned*>(Ah + (gr + 8) * YHS + kb + 8);
        unsigned l0 = *reinterpret_cast<const unsigned*>(Al + gr * YHS + kb);
        unsigned l1 = *reinterpret_cast<const unsigned*>(Al + (gr + 8) * YHS + kb);
        unsigned l2 = *reinterpret_cast<const unsigned*>(Al + gr * YHS + kb + 8);
        unsigned l3 = *reinterpret_cast<const unsigned*>(Al + (gr + 8) * YHS + kb + 8);
        unsigned b0 = *reinterpret_cast<const unsigned*>(BTh + nc * 128 + kb);
        unsigned b1 = *reinterpret_cast<const unsigned*>(BTh + nc * 128 + kb + 8);
        unsigned c0 = *reinterpret_cast<const unsigned*>(BTl + nc * 128 + kb);
        unsigned c1 = *reinterpret_cast<const unsigned*>(BTl + nc * 128 + kb + 8);
        mma16816(d0, d1, d2, d3, a0, a1, a2, a3, b0, b1);
        mma16816(d0, d1, d2, d3, l0, l1, l2, l3, b0, b1);
        mma16816(d0, d1, d2, d3, a0, a1, a2, a3, c0, c1);
    }
}

__device__ __forceinline__ void hilo_store(__half* H, __half* L, int row, int col,
                                           float v0, float v1)
{
    __half2 h = __floats2half2_rn(v0, v1);
    float2 q = __half22float2(h);
    __half2 l = __floats2half2_rn(v0 - q.x, v1 - q.y);
    *reinterpret_cast<unsigned*>(H + row * YHS + col) = *reinterpret_cast<unsigned*>(&h);
    *reinterpret_cast<unsigned*>(L + row * YHS + col) = *reinterpret_cast<unsigned*>(&l);
}

// ---- fused coarse+fine table: 512 blocks x 256 thr ----
__global__ void k_tab(const float* __restrict__ w1, const float* __restrict__ b1,
                      const float* __restrict__ w2, const float* __restrict__ b2)
{
    __shared__ float w1s[32 * 128];
    __shared__ float rbf_s[17 * 32];
    __shared__ float As[17 * 128];
    const float hc = D_MAX / (float)TC;
    const float dc = 30.0f / 299.0f;
    const int t0c = blockIdx.x * 16, tid = threadIdx.x;
    const int tg = tid >> 7, h = tid & 127, T0 = tg * 8;

    float dmin = (float)t0c * hc, dmax = (float)(t0c + 16) * hc;
    int glo = (int)floorf((dmin - 1.4f) / dc); if (glo < 0) glo = 0;
    int ghi = (int)ceilf((dmax + 1.4f) / dc);  if (ghi > NGAUSS - 1) ghi = NGAUSS - 1;
    int ng = ghi - glo + 1; if (ng < 0) ng = 0; if (ng > 32) ng = 32;

    for (int idx = tid; idx < ng * 128; idx += 256) w1s[idx] = w1[glo * 128 + idx];
    for (int idx = tid; idx < 17 * ng; idx += 256) {
        int t = idx / ng, g = idx % ng;
        int tc = min(t0c + t, TC - 1);
        float u = (float)tc * hc - (float)(glo + g) * dc;
        rbf_s[t * 32 + g] = __expf(-10.0f * u * u);
    }
    __syncthreads();

    float acc[9];
#pragma unroll
    for (int t = 0; t < 9; t++) acc[t] = 0.0f;
    for (int g = 0; g < ng; g++) {
        float w = w1s[g * 128 + h];
#pragma unroll
        for (int t = 0; t < 9; t++) acc[t] += rbf_s[(T0 + t) * 32 + g] * w;
    }
    float bb = b1[h];
#pragma unroll
    for (int t = 0; t < 9; t++)
        if (tg == 0 || t > 0) As[(T0 + t) * 128 + h] = sspf(acc[t] + bb);
    __syncthreads();

#pragma unroll
    for (int t = 0; t < 9; t++) acc[t] = 0.0f;
    for (int k = 0; k < 128; k++) {
        float w = __ldg(&w2[k * 128 + h]);
#pragma unroll
        for (int t = 0; t < 9; t++) acc[t] += As[(T0 + t) * 128 + k] * w;
    }
    float b2v = b2[h];
    __syncthreads();
#pragma unroll
    for (int t = 0; t < 9; t++)
        if (tg == 0 || t > 0) As[(T0 + t) * 128 + h] = acc[t] + b2v;
    __syncthreads();

    for (int task = tid; task < 4096; task += 256) {
        int rho = task >> 5, h4 = task & 31;
        int u = rho >> 3;
        float fr = (float)(rho & 7) * 0.125f;
        float4 a = *reinterpret_cast<const float4*>(As + u * 128 + h4 * 4);
        float4 b = *reinterpret_cast<const float4*>(As + (u + 1) * 128 + h4 * 4);
        __half2 h01 = __floats2half2_rn(a.x + fr * (b.x - a.x), a.y + fr * (b.y - a.y));
        __half2 h23 = __floats2half2_rn(a.z + fr * (b.z - a.z), a.w + fr * (b.w - a.w));
        uint2 o;
        o.x = *reinterpret_cast<unsigned*>(&h01);
        o.y = *reinterpret_cast<unsigned*>(&h23);
        g_tabn[(blockIdx.x * 128 + rho) * 32 + h4] = o;
    }
}

// ---- fused setup (R12 roles; restores fp16 f mirror) ----
__global__ void k_setup(const int* __restrict__ z, const float* __restrict__ emb,
                        const float* __restrict__ w_in2f, const float* __restrict__ w_out,
                        const float* __restrict__ b_out, const float* __restrict__ w_f2out,
                        const float* __restrict__ w_aw1, const float* __restrict__ r)
{
    extern __shared__ float sm[];
    float* ws = sm;            // [128][128]
    float* xs = sm + 16384;    // [16][128]
    const int bx = blockIdx.x, tid = threadIdx.x;

    if (bx >= 277) {           // distance -> table index, one block per batch
        float* rs = sm;
        const int b = bx - 277;
        if (tid < 128) {
            const float* rp = r + (b * 128 + tid) * 3;
            rs[tid] = rp[0]; rs[128 + tid] = rp[1]; rs[256 + tid] = rp[2];
        }
        __syncthreads();
        const float inv_h = (float)TF / D_MAX;
        for (int task = tid; task < 16384; task += 256) {
            int i = task >> 7, j = task & 127;
            float dx = rs[i] - rs[j], dy = rs[128 + i] - rs[128 + j], dz = rs[256 + i] - rs[256 + j];
            float d = sqrtf(dx * dx + dy * dy + dz * dz + 1e-12f);
            g_idx[b * 16384 + task] =
                (unsigned short)fminf(d * inv_h + 0.5f, (float)(TF - 1));
        }
        return;
    }
    if (bx >= 265) {
        const float* src; __half *dh, *dl;
        int role = (bx - 265) >> 2, base = ((bx - 265) & 3) * 4096;
        if (role == 0)      { src = w_f2out; dh = g_wf2T_h;  dl = g_wf2T_l; }
        else if (role == 1) { src = w_out;   dh = g_woutT_h; dl = g_woutT_l; }
        else                { src = w_aw1;   dh = g_aw1T_h;  dl = g_aw1T_l; }
        for (int e = base + tid; e < base + 4096; e += 256) {
            int n = e >> 7, k = e & 127;
            float v = src[k * 128 + n];
            __half hh = __float2half_rn(v);
            dh[e] = hh;
            dl[e] = __float2half_rn(v - __half2float(hh));
        }
        return;
    }

    for (int idx = tid; idx < 16384; idx += 256) ws[idx] = w_in2f[idx];
    if (bx < 256) {
        int r0 = bx * 16;
        for (int idx = tid; idx < 2048; idx += 256) {
            int i = idx >> 7, h = idx & 127;
            int zi = z[r0 + i];
            float v = emb[zi * 128 + h];
            xs[idx] = v;
            g_x[r0 * 128 + idx] = v;
            g_ysum[r0 * 128 + idx] = 0.0f;
        }
    } else if (bx < 264) {
        int r0 = (bx - 256) * 16;
        for (int idx = tid; idx < 2048; idx += 256) xs[idx] = w_out[r0 * 128 + idx];
    }
    __syncthreads();

    if (bx == 264) {
        if (tid < 128) {
            float s = 0.0f;
            for (int m = 0; m < 128; m++) s += __ldg(&b_out[m]) * ws[m * 128 + tid];
            g_fbias[tid] = s;
        }
        return;
    }
    const int rg = tid >> 5, hg = tid & 31;
    float a[2][4];
#pragma unroll
    for (int rr = 0; rr < 2; rr++)
#pragma unroll
        for (int c = 0; c < 4; c++) a[rr][c] = 0.0f;
    for (int k = 0; k < 128; k++) {
        float4 wb = *reinterpret_cast<const float4*>(ws + k * 128 + hg * 4);
        float y0 = xs[(rg * 2) * 128 + k], y1 = xs[(rg * 2 + 1) * 128 + k];
        a[0][0] += y0 * wb.x; a[0][1] += y0 * wb.y; a[0][2] += y0 * wb.z; a[0][3] += y0 * wb.w;
        a[1][0] += y1 * wb.x; a[1][1] += y1 * wb.y; a[1][2] += y1 * wb.z; a[1][3] += y1 * wb.w;
    }
    if (bx < 256) {
#pragma unroll
        for (int rr = 0; rr < 2; rr++) {
            int row = bx * 16 + rg * 2 + rr;
            *reinterpret_cast<float4*>(g_fA + row * 128 + hg * 4) =
                make_float4(a[rr][0], a[rr][1], a[rr][2], a[rr][3]);
            __half2 h01 = __floats2half2_rn(a[rr][0], a[rr][1]);
            __half2 h23 = __floats2half2_rn(a[rr][2], a[rr][3]);
            uint2 hv;
            hv.x = *reinterpret_cast<unsigned*>(&h01);
            hv.y = *reinterpret_cast<unsigned*>(&h23);
            *reinterpret_cast<uint2*>(g_fhA + row * 128 + hg * 4) = hv;
        }
    } else {
        __syncthreads();
#pragma unroll
        for (int rr = 0; rr < 2; rr++)
#pragma unroll
            for (int c = 0; c < 4; c++)
                xs[(rg * 2 + rr) * 128 + hg * 4 + c] = a[rr][c];
        __syncthreads();
        int r0 = (bx - 256) * 16;
        for (int e = tid; e < 2048; e += 256) {
            int n = e >> 4, q = e & 15;
            float v = xs[q * 128 + n];
            __half hh = __float2half_rn(v);
            g_comboT_h[n * 128 + r0 + q] = hh;
            g_comboT_l[n * 128 + r0 + q] = __float2half_rn(v - __half2float(hh));
        }
    }
}

// ---- gather: y[i,h] = sum_j Wtab[idx(i,j)][h] * f[j,h]. grid (16,32) x 256 ----
__global__ void __launch_bounds__(256) k_gather(int flag)
{
    __shared__ __align__(16) __half f_s[128 * 128];   // 32 KB
    __shared__ unsigned idx_s[8 * 64];                // 2 KB
    const int it = blockIdx.x, b = blockIdx.y, tid = threadIdx.x;
    const __half* fh = (flag ? g_fhB : g_fhA) + b * 16384;

    {
        const unsigned* gi = reinterpret_cast<const unsigned*>(g_idx + (b * 128 + it * 8) * 128);
        idx_s[tid] = gi[tid];
        idx_s[tid + 256] = gi[tid + 256];
    }
    for (int i2 = tid; i2 < 2048; i2 += 256)
        reinterpret_cast<uint4*>(f_s)[i2] = reinterpret_cast<const uint4*>(fh)[i2];
    __syncthreads();

    const int w = tid >> 5, lane = tid & 31;
    const unsigned* ip = idx_s + w * 64;
    float a0 = 0.f, a1 = 0.f, a2 = 0.f, a3 = 0.f;
#pragma unroll 8
    for (int j2 = 0; j2 < 64; j2++) {
        unsigned pr = ip[j2];
        unsigned t0 = pr & 0xFFFFu, t1 = pr >> 16;
        uint2 u0 = g_tabn[t0 * 32 + lane];
        uint2 u1 = g_tabn[t1 * 32 + lane];
        uint2 fv0 = *reinterpret_cast<const uint2*>(f_s + (j2 * 2) * 128 + lane * 4);
        uint2 fv1 = *reinterpret_cast<const uint2*>(f_s + (j2 * 2 + 1) * 128 + lane * 4);
        {
            __half2 w01 = *reinterpret_cast<__half2*>(&u0.x);
            __half2 w23 = *reinterpret_cast<__half2*>(&u0.y);
            __half2 f01 = *reinterpret_cast<__half2*>(&fv0.x);
            __half2 f23 = *reinterpret_cast<__half2*>(&fv0.y);
            float2 pw0 = __half22float2(w01), pw1 = __half22float2(w23);
            float2 pf0 = __half22float2(f01), pf1 = __half22float2(f23);
            a0 = fmaf(pw0.x, pf0.x, a0);
            a1 = fmaf(pw0.y, pf0.y, a1);
            a2 = fmaf(pw1.x, pf1.x, a2);
            a3 = fmaf(pw1.y, pf1.y, a3);
        }
        {
            __half2 w01 = *reinterpret_cast<__half2*>(&u1.x);
            __half2 w23 = *reinterpret_cast<__half2*>(&u1.y);
            __half2 f01 = *reinterpret_cast<__half2*>(&fv1.x);
            __half2 f23 = *reinterpret_cast<__half2*>(&fv1.y);
            float2 pw0 = __half22float2(w01), pw1 = __half22float2(w23);
            float2 pf0 = __half22float2(f01), pf1 = __half22float2(f23);
            a0 = fmaf(pw0.x, pf0.x, a0);
            a1 = fmaf(pw0.y, pf0.y, a1);
            a2 = fmaf(pw1.x, pf1.x, a2);
            a3 = fmaf(pw1.y, pf1.y, a3);
        }
    }
    int i = it * 8 + w;
    *reinterpret_cast<float4*>(g_y + (b * 128 + i) * 128 + lane * 4) =
        make_float4(a0, a1, a2, a3);
}

// ---- epilogue (split-mma) + mode-2 readout. grid (8,32) x 512 ----
__global__ void __launch_bounds__(512)
k_epi(const float* __restrict__ b_f2out, const float* __restrict__ b_out,
      const float* __restrict__ b_aw1, const float* __restrict__ w_aw2,
      const float* __restrict__ b_aw2, float* __restrict__ out, int mode)
{
    __shared__ __align__(16) __half yh[16 * YHS], yl[16 * YHS];
    __shared__ __align__(16) __half y2h[16 * YHS], y2l[16 * YHS];
    __shared__ float bias1[128], fb_s[128], baw1[128], w2ro[128], red[16];
    const int it = blockIdx.x, b = blockIdx.y, tid = threadIdx.x;
    const int flag = (mode == 1) ? 1 : 0;
    const float* f_in  = flag ? g_fB : g_fA;
    float*       f_out = flag ? g_fA : g_fB;
    __half*      fh_out = flag ? g_fhA : g_fhB;

    if (tid < 128) bias1[tid] = b_f2out[tid];
    else if (tid < 256) fb_s[tid - 128] = (mode == 2) ? b_out[tid - 128] : g_fbias[tid - 128];
    else if (tid < 384) baw1[tid - 256] = b_aw1[tid - 256];
    else w2ro[tid - 384] = w_aw2[tid - 384];
    if (tid < 16) red[tid] = 0.0f;
    {
        int row = tid >> 5, h4 = tid & 31;
        float4 yv = *reinterpret_cast<const float4*>(g_y + (b * 128 + it * 16 + row) * 128 + h4 * 4);
        hilo_store(yh, yl, row, h4 * 4, yv.x, yv.y);
        hilo_store(yh, yl, row, h4 * 4 + 2, yv.z, yv.w);
    }
    __syncthreads();

    const int w = tid >> 5, lane = tid & 31;
    const int gr = lane >> 2, ct = lane & 3, n0 = w * 8;
    const int nc = n0 + gr;
    const int c0 = n0 + ct * 2;
    const int row0 = gr, row1 = gr + 8;
    float d0 = 0.f, d1 = 0.f, d2 = 0.f, d3 = 0.f;
    split_gemm(d0, d1, d2, d3, yh, yl, g_wf2T_h, g_wf2T_l, gr, ct, nc);
    float s0, s1, s2, s3;
    {
        float v0 = sspf(d0 + bias1[c0]), v1 = sspf(d1 + bias1[c0 + 1]);
        float v2 = sspf(d2 + bias1[c0]), v3 = sspf(d3 + bias1[c0 + 1]);
        int gr0 = (b * 128 + it * 16 + row0) * 128 + c0;
        int gr1 = (b * 128 + it * 16 + row1) * 128 + c0;
        float2 t0 = *reinterpret_cast<float2*>(g_ysum + gr0);
        float2 t1 = *reinterpret_cast<float2*>(g_ysum + gr1);
        s0 = t0.x + v0; s1 = t0.y + v1; s2 = t1.x + v2; s3 = t1.y + v3;
        __syncthreads();
        if (mode != 2) {
            *reinterpret_cast<float2*>(g_ysum + gr0) = make_float2(s0, s1);
            *reinterpret_cast<float2*>(g_ysum + gr1) = make_float2(s2, s3);
            hilo_store(y2h, y2l, row0, c0, v0, v1);
            hilo_store(y2h, y2l, row1, c0, v2, v3);
        } else {
            hilo_store(y2h, y2l, row0, c0, s0, s1);   // A = final ysum
            hilo_store(y2h, y2l, row1, c0, s2, s3);
        }
    }
    __syncthreads();

    if (mode != 2) {
        d0 = d1 = d2 = d3 = 0.f;
        split_gemm(d0, d1, d2, d3, y2h, y2l, g_comboT_h, g_comboT_l, gr, ct, nc);
        int gr0 = (b * 128 + it * 16 + row0) * 128 + c0;
        int gr1 = (b * 128 + it * 16 + row1) * 128 + c0;
        float2 fi0 = *reinterpret_cast<const float2*>(f_in + gr0);
        float2 fi1 = *reinterpret_cast<const float2*>(f_in + gr1);
        float fb0 = fb_s[c0], fb1 = fb_s[c0 + 1];
        float o0 = fi0.x + fb0 + d0, o1 = fi0.y + fb1 + d1;
        float o2 = fi1.x + fb0 + d2, o3 = fi1.y + fb1 + d3;
        *reinterpret_cast<float2*>(f_out + gr0) = make_float2(o0, o1);
        *reinterpret_cast<float2*>(f_out + gr1) = make_float2(o2, o3);
        __half2 q01 = __floats2half2_rn(o0, o1);
        __half2 q23 = __floats2half2_rn(o2, o3);
        *reinterpret_cast<unsigned*>(fh_out + gr0) = *reinterpret_cast<unsigned*>(&q01);
        *reinterpret_cast<unsigned*>(fh_out + gr1) = *reinterpret_cast<unsigned*>(&q23);
        return;
    }

    // ---- mode 2: readout ----
    d0 = d1 = d2 = d3 = 0.f;
    split_gemm(d0, d1, d2, d3, y2h, y2l, g_woutT_h, g_woutT_l, gr, ct, nc);
    {
        int gr0 = (b * 128 + it * 16 + row0) * 128 + c0;
        int gr1 = (b * 128 + it * 16 + row1) * 128 + c0;
        float2 x0a = *reinterpret_cast<const float2*>(g_x + gr0);
        float2 x0b = *reinterpret_cast<const float2*>(g_x + gr1);
        float bo0 = 3.0f * fb_s[c0], bo1 = 3.0f * fb_s[c0 + 1];
        hilo_store(yh, yl, row0, c0, x0a.x + d0 + bo0, x0a.y + d1 + bo1);
        hilo_store(yh, yl, row1, c0, x0b.x + d2 + bo0, x0b.y + d3 + bo1);
    }
    __syncthreads();

    d0 = d1 = d2 = d3 = 0.f;
    split_gemm(d0, d1, d2, d3, yh, yl, g_aw1T_h, g_aw1T_l, gr, ct, nc);
    {
        float t0 = sspf(d0 + baw1[c0]), t1 = sspf(d1 + baw1[c0 + 1]);
        float t2 = sspf(d2 + baw1[c0]), t3 = sspf(d3 + baw1[c0 + 1]);
        float w0 = w2ro[c0], w1 = w2ro[c0 + 1];
        atomicAdd(&red[row0], t0 * w0 + t1 * w1);
        atomicAdd(&red[row1], t2 * w0 + t3 * w1);
    }
    __syncthreads();
    if (tid < 16)
        out[b * 128 + it * 16 + tid] = red[tid] + b_aw2[0];
}

extern "C" void kernel_launch(void* const* d_in, const int* in_sizes, int n_in,
                              void* d_out, int out_size)
{
    const int*   z       = (const int*)  d_in[0];
    const float* r       = (const float*)d_in[1];
    const float* emb     = (const float*)d_in[2];
    const float* w_in2f  = (const float*)d_in[3];
    const float* w_f1    = (const float*)d_in[4];
    const float* b_f1    = (const float*)d_in[5];
    const float* w_f2    = (const float*)d_in[6];
    const float* b_f2    = (const float*)d_in[7];
    const float* w_f2out = (const float*)d_in[8];
    const float* b_f2out = (const float*)d_in[9];
    const float* w_out   = (const float*)d_in[10];
    const float* b_out   = (const float*)d_in[11];
    const float* w_aw1   = (const float*)d_in[12];
    const float* b_aw1   = (const float*)d_in[13];
    const float* w_aw2   = (const float*)d_in[14];
    const float* b_aw2   = (const float*)d_in[15];
    float* out = (float*)d_out;

    cudaFuncSetAttribute(k_setup, cudaFuncAttributeMaxDynamicSharedMemorySize, 73728);

    k_tab<<<512, 256>>>(w_f1, b_f1, w_f2, b_f2);
    k_setup<<<309, 256, 73728>>>(z, emb, w_in2f, w_out, b_out, w_f2out, w_aw1, r);
    for (int it = 0; it < 3; it++) {
        k_gather<<<dim3(16, 32), 256>>>(it & 1);
        k_epi<<<dim3(8, 32), 512>>>(b_f2out, b_out, b_aw1, w_aw2, b_aw2, out, it);
    }
}

// round 16
// speedup vs baseline: 1.1060x; 1.0671x over previous
#include <cuda_runtime.h>
#include <cuda_fp16.h>

#define TC 8192
#define TF 65536
#define D_MAX 36.0f
#define NGAUSS 300

__device__ __align__(16) uint2  g_tabn[TF * 32];        // fine fp16 nearest table (16 MB)
__device__ __align__(16) float  g_x[4096 * 128];
__device__ __align__(16) float  g_fA[4096 * 128];
__device__ __align__(16) float  g_fB[4096 * 128];
__device__ __align__(16) __half g_fhA[4096 * 128];      // fp16 f mirrors for gather
__device__ __align__(16) __half g_fhB[4096 * 128];
__device__ __align__(16) float  g_y[4096 * 128];
__device__ __align__(16) float  g_ysum[4096 * 128];
__device__ __align__(16) float  g_fbias[128];
__device__ __align__(16) unsigned short g_idx[32 * 128 * 128];  // table indices (1 MB)
__device__ __align__(16) __half g_wf2T_h[128 * 128];    // w_f2out^T hi/lo fp16 [n][k]
__device__ __align__(16) __half g_wf2T_l[128 * 128];
__device__ __align__(16) __half g_comboT_h[128 * 128];  // (w_out@w_in2f)^T hi/lo
__device__ __align__(16) __half g_comboT_l[128 * 128];
__device__ __align__(16) __half g_woutT_h[128 * 128];   // w_out^T hi/lo
__device__ __align__(16) __half g_woutT_l[128 * 128];
__device__ __align__(16) __half g_aw1T_h[128 * 128];    // w_aw1^T hi/lo
__device__ __align__(16) __half g_aw1T_l[128 * 128];

__device__ __forceinline__ float sspf(float x) {
    return fmaxf(x, 0.0f) + log1pf(__expf(-fabsf(x))) - 0.69314718055994531f;
}

__device__ __forceinline__ void mma16816(float& d0, float& d1, float& d2, float& d3,
                                         unsigned a0, unsigned a1, unsigned a2, unsigned a3,
                                         unsigned b0, unsigned b1)
{
    asm volatile(
        "mma.sync.aligned.m16n8k16.row.col.f32.f16.f16.f32 "
        "{%0,%1,%2,%3}, {%4,%5,%6,%7}, {%8,%9}, {%0,%1,%2,%3};\n"
        : "+f"(d0), "+f"(d1), "+f"(d2), "+f"(d3)
        : "r"(a0), "r"(a1), "r"(a2), "r"(a3), "r"(b0), "r"(b1));
}

#define YHS 136
// split-precision GEMM: B prefetched to registers (MLP~32), dual accumulator chains
__device__ __forceinline__ void split_gemm(float& d0, float& d1, float& d2, float& d3,
                                           const __half* Ah, const __half* Al,
                                           const __half* BTh, const __half* BTl,
                                           int gr, int ct, int nc)
{
    unsigned bh[16], bl[16];
#pragma unroll
    for (int ks = 0; ks < 8; ks++) {
        int kb = ks * 16 + ct * 2;
        bh[ks * 2]     = *reinterpret_cast<const unsigned*>(BTh + nc * 128 + kb);
        bh[ks * 2 + 1] = *reinterpret_cast<const unsigned*>(BTh + nc * 128 + kb + 8);
        bl[ks * 2]     = *reinterpret_cast<const unsigned*>(BTl + nc * 128 + kb);
        bl[ks * 2 + 1] = *reinterpret_cast<const unsigned*>(BTl + nc * 128 + kb + 8);
    }
    float e0 = 0.f, e1 = 0.f, e2 = 0.f, e3 = 0.f;
#pragma unroll
    for (int ks = 0; ks < 8; ks++) {
        int kb = ks * 16 + ct * 2;
        unsigned a0 = *reinterpret_cast<const unsigned*>(Ah + gr * YHS + kb);
        unsigned a1 = *reinterpret_cast<const unsigned*>(Ah + (gr + 8) * YHS + kb);
        unsigned a2 = *reinterpret_cast<const unsigned*>(Ah + gr * YHS + kb + 8);
        unsigned a3 = *reinterpret_cast<const unsigned*>(Ah + (gr + 8) * YHS + kb + 8);
        unsigned l0 = *reinterpret_cast<const unsigned*>(Al + gr * YHS + kb);
        unsigned l1 = *reinterpret_cast<const unsigned*>(Al + (gr + 8) * YHS + kb);
        unsigned l2 = *reinterpret_cast<const unsigned*>(Al + gr * YHS + kb + 8);
        unsigned l3 = *reinterpret_cast<const unsigned*>(Al + (gr + 8) * YHS + kb + 8);
        if (ks & 1) {
            mma16816(d0, d1, d2, d3, a0, a1, a2, a3, bh[ks * 2], bh[ks * 2 + 1]);
            mma16816(d0, d1, d2, d3, l0, l1, l2, l3, bh[ks * 2], bh[ks * 2 + 1]);
            mma16816(d0, d1, d2, d3, a0, a1, a2, a3, bl[ks * 2], bl[ks * 2 + 1]);
        } else {
            mma16816(e0, e1, e2, e3, a0, a1, a2, a3, bh[ks * 2], bh[ks * 2 + 1]);
            mma16816(e0, e1, e2, e3, l0, l1, l2, l3, bh[ks * 2], bh[ks * 2 + 1]);
            mma16816(e0, e1, e2, e3, a0, a1, a2, a3, bl[ks * 2], bl[ks * 2 + 1]);
        }
    }
    d0 += e0; d1 += e1; d2 += e2; d3 += e3;
}

__device__ __forceinline__ void hilo_store(__half* H, __half* L, int row, int col,
                                           float v0, float v1)
{
    __half2 h = __floats2half2_rn(v0, v1);
    float2 q = __half22float2(h);
    __half2 l = __floats2half2_rn(v0 - q.x, v1 - q.y);
    *reinterpret_cast<unsigned*>(H + row * YHS + col) = *reinterpret_cast<unsigned*>(&h);
    *reinterpret_cast<unsigned*>(L + row * YHS + col) = *reinterpret_cast<unsigned*>(&l);
}

// ---- merged init: blocks 0-511 = table build; 512-820 = setup roles ----
__global__ void k_init(const int* __restrict__ z, const float* __restrict__ emb,
                       const float* __restrict__ w_in2f, const float* __restrict__ w_out,
                       const float* __restrict__ b_out, const float* __restrict__ w_f2out,
                       const float* __restrict__ w_aw1, const float* __restrict__ r,
                       const float* __restrict__ w1, const float* __restrict__ b1,
                       const float* __restrict__ w2, const float* __restrict__ b2)
{
    extern __shared__ float sm[];
    const int bx = blockIdx.x, tid = threadIdx.x;

    if (bx < 512) {
        // ======== table build (coarse rows in smem -> fine fp16 rows) ========
        float* w1s   = sm;                  // 32*128
        float* rbf_s = sm + 4096;           // 17*32
        float* As    = rbf_s + 544;         // 17*128
        const float hc = D_MAX / (float)TC;
        const float dc = 30.0f / 299.0f;
        const int t0c = bx * 16;
        const int tg = tid >> 7, h = tid & 127, T0 = tg * 8;

        float dmin = (float)t0c * hc, dmax = (float)(t0c + 16) * hc;
        int glo = (int)floorf((dmin - 1.4f) / dc); if (glo < 0) glo = 0;
        int ghi = (int)ceilf((dmax + 1.4f) / dc);  if (ghi > NGAUSS - 1) ghi = NGAUSS - 1;
        int ng = ghi - glo + 1; if (ng < 0) ng = 0; if (ng > 32) ng = 32;

        for (int idx = tid; idx < ng * 128; idx += 256) w1s[idx] = w1[glo * 128 + idx];
        for (int idx = tid; idx < 17 * ng; idx += 256) {
            int t = idx / ng, g = idx % ng;
            int tc = min(t0c + t, TC - 1);
            float u = (float)tc * hc - (float)(glo + g) * dc;
            rbf_s[t * 32 + g] = __expf(-10.0f * u * u);
        }
        __syncthreads();

        float acc[9];
#pragma unroll
        for (int t = 0; t < 9; t++) acc[t] = 0.0f;
        for (int g = 0; g < ng; g++) {
            float w = w1s[g * 128 + h];
#pragma unroll
            for (int t = 0; t < 9; t++) acc[t] += rbf_s[(T0 + t) * 32 + g] * w;
        }
        float bb = b1[h];
#pragma unroll
        for (int t = 0; t < 9; t++)
            if (tg == 0 || t > 0) As[(T0 + t) * 128 + h] = sspf(acc[t] + bb);
        __syncthreads();

#pragma unroll
        for (int t = 0; t < 9; t++) acc[t] = 0.0f;
        for (int k = 0; k < 128; k++) {
            float w = __ldg(&w2[k * 128 + h]);
#pragma unroll
            for (int t = 0; t < 9; t++) acc[t] += As[(T0 + t) * 128 + k] * w;
        }
        float b2v = b2[h];
        __syncthreads();
#pragma unroll
        for (int t = 0; t < 9; t++)
            if (tg == 0 || t > 0) As[(T0 + t) * 128 + h] = acc[t] + b2v;
        __syncthreads();

        for (int task = tid; task < 4096; task += 256) {
            int rho = task >> 5, h4 = task & 31;
            int u = rho >> 3;
            float fr = (float)(rho & 7) * 0.125f;
            float4 a = *reinterpret_cast<const float4*>(As + u * 128 + h4 * 4);
            float4 b = *reinterpret_cast<const float4*>(As + (u + 1) * 128 + h4 * 4);
            __half2 h01 = __floats2half2_rn(a.x + fr * (b.x - a.x), a.y + fr * (b.y - a.y));
            __half2 h23 = __floats2half2_rn(a.z + fr * (b.z - a.z), a.w + fr * (b.w - a.w));
            uint2 o;
            o.x = *reinterpret_cast<unsigned*>(&h01);
            o.y = *reinterpret_cast<unsigned*>(&h23);
            g_tabn[(bx * 128 + rho) * 32 + h4] = o;
        }
        return;
    }

    // ======== setup roles (sx = bx - 512) ========
    const int sx = bx - 512;
    float* ws = sm;            // [128][128]
    float* xs = sm + 16384;    // [16][128]

    if (sx >= 277) {           // distance -> table index, one block per batch
        float* rs = sm;
        const int b = sx - 277;
        if (tid < 128) {
            const float* rp = r + (b * 128 + tid) * 3;
            rs[tid] = rp[0]; rs[128 + tid] = rp[1]; rs[256 + tid] = rp[2];
        }
        __syncthreads();
        const float inv_h = (float)TF / D_MAX;
        for (int task = tid; task < 16384; task += 256) {
            int i = task >> 7, j = task & 127;
            float dx = rs[i] - rs[j], dy = rs[128 + i] - rs[128 + j], dz = rs[256 + i] - rs[256 + j];
            float d = sqrtf(dx * dx + dy * dy + dz * dz + 1e-12f);
            g_idx[b * 16384 + task] =
                (unsigned short)fminf(d * inv_h + 0.5f, (float)(TF - 1));
        }
        return;
    }
    if (sx >= 265) {
        const float* src; __half *dh, *dl;
        int role = (sx - 265) >> 2, base = ((sx - 265) & 3) * 4096;
        if (role == 0)      { src = w_f2out; dh = g_wf2T_h;  dl = g_wf2T_l; }
        else if (role == 1) { src = w_out;   dh = g_woutT_h; dl = g_woutT_l; }
        else                { src = w_aw1;   dh = g_aw1T_h;  dl = g_aw1T_l; }
        for (int e = base + tid; e < base + 4096; e += 256) {
            int n = e >> 7, k = e & 127;
            float v = src[k * 128 + n];
            __half hh = __float2half_rn(v);
            dh[e] = hh;
            dl[e] = __float2half_rn(v - __half2float(hh));
        }
        return;
    }

    for (int idx = tid; idx < 16384; idx += 256) ws[idx] = w_in2f[idx];
    if (sx < 256) {
        int r0 = sx * 16;
        for (int idx = tid; idx < 2048; idx += 256) {
            int i = idx >> 7, h = idx & 127;
            int zi = z[r0 + i];
            float v = emb[zi * 128 + h];
            xs[idx] = v;
            g_x[r0 * 128 + idx] = v;
            g_ysum[r0 * 128 + idx] = 0.0f;
        }
    } else if (sx < 264) {
        int r0 = (sx - 256) * 16;
        for (int idx = tid; idx < 2048; idx += 256) xs[idx] = w_out[r0 * 128 + idx];
    }
    __syncthreads();

    if (sx == 264) {
        if (tid < 128) {
            float s = 0.0f;
            for (int m = 0; m < 128; m++) s += __ldg(&b_out[m]) * ws[m * 128 + tid];
            g_fbias[tid] = s;
        }
        return;
    }
    const int rg = tid >> 5, hg = tid & 31;
    float a[2][4];
#pragma unroll
    for (int rr = 0; rr < 2; rr++)
#pragma unroll
        for (int c = 0; c < 4; c++) a[rr][c] = 0.0f;
    for (int k = 0; k < 128; k++) {
        float4 wb = *reinterpret_cast<const float4*>(ws + k * 128 + hg * 4);
        float y0 = xs[(rg * 2) * 128 + k], y1 = xs[(rg * 2 + 1) * 128 + k];
        a[0][0] += y0 * wb.x; a[0][1] += y0 * wb.y; a[0][2] += y0 * wb.z; a[0][3] += y0 * wb.w;
        a[1][0] += y1 * wb.x; a[1][1] += y1 * wb.y; a[1][2] += y1 * wb.z; a[1][3] += y1 * wb.w;
    }
    if (sx < 256) {
#pragma unroll
        for (int rr = 0; rr < 2; rr++) {
            int row = sx * 16 + rg * 2 + rr;
            *reinterpret_cast<float4*>(g_fA + row * 128 + hg * 4) =
                make_float4(a[rr][0], a[rr][1], a[rr][2], a[rr][3]);
            __half2 h01 = __floats2half2_rn(a[rr][0], a[rr][1]);
            __half2 h23 = __floats2half2_rn(a[rr][2], a[rr][3]);
            uint2 hv;
            hv.x = *reinterpret_cast<unsigned*>(&h01);
            hv.y = *reinterpret_cast<unsigned*>(&h23);
            *reinterpret_cast<uint2*>(g_fhA + row * 128 + hg * 4) = hv;
        }
    } else {
        __syncthreads();
#pragma unroll
        for (int rr = 0; rr < 2; rr++)
#pragma unroll
            for (int c = 0; c < 4; c++)
                xs[(rg * 2 + rr) * 128 + hg * 4 + c] = a[rr][c];
        __syncthreads();
        int r0 = (sx - 256) * 16;
        for (int e = tid; e < 2048; e += 256) {
            int n = e >> 4, q = e & 15;
            float v = xs[q * 128 + n];
            __half hh = __float2half_rn(v);
            g_comboT_h[n * 128 + r0 + q] = hh;
            g_comboT_l[n * 128 + r0 + q] = __float2half_rn(v - __half2float(hh));
        }
    }
}

// ---- gather: y[i,h] = sum_j Wtab[idx(i,j)][h] * f[j,h]. grid (16,32) x 256 ----
__global__ void __launch_bounds__(256) k_gather(int flag)
{
    __shared__ __align__(16) __half f_s[128 * 128];   // 32 KB
    __shared__ unsigned idx_s[8 * 64];                // 2 KB
    const int it = blockIdx.x, b = blockIdx.y, tid = threadIdx.x;
    const __half* fh = (flag ? g_fhB : g_fhA) + b * 16384;

    {
        const unsigned* gi = reinterpret_cast<const unsigned*>(g_idx + (b * 128 + it * 8) * 128);
        idx_s[tid] = gi[tid];
        idx_s[tid + 256] = gi[tid + 256];
    }
    for (int i2 = tid; i2 < 2048; i2 += 256)
        reinterpret_cast<uint4*>(f_s)[i2] = reinterpret_cast<const uint4*>(fh)[i2];
    __syncthreads();

    const int w = tid >> 5, lane = tid & 31;
    const unsigned* ip = idx_s + w * 64;
    float a0 = 0.f, a1 = 0.f, a2 = 0.f, a3 = 0.f;
#pragma unroll 8
    for (int j2 = 0; j2 < 64; j2++) {
        unsigned pr = ip[j2];
        unsigned t0 = pr & 0xFFFFu, t1 = pr >> 16;
        uint2 u0 = g_tabn[t0 * 32 + lane];
        uint2 u1 = g_tabn[t1 * 32 + lane];
        uint2 fv0 = *reinterpret_cast<const uint2*>(f_s + (j2 * 2) * 128 + lane * 4);
        uint2 fv1 = *reinterpret_cast<const uint2*>(f_s + (j2 * 2 + 1) * 128 + lane * 4);
        {
            __half2 w01 = *reinterpret_cast<__half2*>(&u0.x);
            __half2 w23 = *reinterpret_cast<__half2*>(&u0.y);
            __half2 f01 = *reinterpret_cast<__half2*>(&fv0.x);
            __half2 f23 = *reinterpret_cast<__half2*>(&fv0.y);
            float2 pw0 = __half22float2(w01), pw1 = __half22float2(w23);
            float2 pf0 = __half22float2(f01), pf1 = __half22float2(f23);
            a0 = fmaf(pw0.x, pf0.x, a0);
            a1 = fmaf(pw0.y, pf0.y, a1);
            a2 = fmaf(pw1.x, pf1.x, a2);
            a3 = fmaf(pw1.y, pf1.y, a3);
        }
        {
            __half2 w01 = *reinterpret_cast<__half2*>(&u1.x);
            __half2 w23 = *reinterpret_cast<__half2*>(&u1.y);
            __half2 f01 = *reinterpret_cast<__half2*>(&fv1.x);
            __half2 f23 = *reinterpret_cast<__half2*>(&fv1.y);
            float2 pw0 = __half22float2(w01), pw1 = __half22float2(w23);
            float2 pf0 = __half22float2(f01), pf1 = __half22float2(f23);
            a0 = fmaf(pw0.x, pf0.x, a0);
            a1 = fmaf(pw0.y, pf0.y, a1);
            a2 = fmaf(pw1.x, pf1.x, a2);
            a3 = fmaf(pw1.y, pf1.y, a3);
        }
    }
    int i = it * 8 + w;
    *reinterpret_cast<float4*>(g_y + (b * 128 + i) * 128 + lane * 4) =
        make_float4(a0, a1, a2, a3);
}

// ---- epilogue (split-mma, B prefetched) + mode-2 readout. grid (8,32) x 512 ----
__global__ void __launch_bounds__(512)
k_epi(const float* __restrict__ b_f2out, const float* __restrict__ b_out,
      const float* __restrict__ b_aw1, const float* __restrict__ w_aw2,
      const float* __restrict__ b_aw2, float* __restrict__ out, int mode)
{
    __shared__ __align__(16) __half yh[16 * YHS], yl[16 * YHS];
    __shared__ __align__(16) __half y2h[16 * YHS], y2l[16 * YHS];
    __shared__ float bias1[128], fb_s[128], baw1[128], w2ro[128], red[16];
    const int it = blockIdx.x, b = blockIdx.y, tid = threadIdx.x;
    const int flag = (mode == 1) ? 1 : 0;
    const float* f_in  = flag ? g_fB : g_fA;
    float*       f_out = flag ? g_fA : g_fB;
    __half*      fh_out = flag ? g_fhA : g_fhB;

    if (tid < 128) bias1[tid] = b_f2out[tid];
    else if (tid < 256) fb_s[tid - 128] = (mode == 2) ? b_out[tid - 128] : g_fbias[tid - 128];
    else if (tid < 384) baw1[tid - 256] = b_aw1[tid - 256];
    else w2ro[tid - 384] = w_aw2[tid - 384];
    if (tid < 16) red[tid] = 0.0f;
    {
        int row = tid >> 5, h4 = tid & 31;
        float4 yv = *reinterpret_cast<const float4*>(g_y + (b * 128 + it * 16 + row) * 128 + h4 * 4);
        hilo_store(yh, yl, row, h4 * 4, yv.x, yv.y);
        hilo_store(yh, yl, row, h4 * 4 + 2, yv.z, yv.w);
    }
    __syncthreads();

    const int w = tid >> 5, lane = tid & 31;
    const int gr = lane >> 2, ct = lane & 3, n0 = w * 8;
    const int nc = n0 + gr;
    const int c0 = n0 + ct * 2;
    const int row0 = gr, row1 = gr + 8;
    float d0 = 0.f, d1 = 0.f, d2 = 0.f, d3 = 0.f;
    split_gemm(d0, d1, d2, d3, yh, yl, g_wf2T_h, g_wf2T_l, gr, ct, nc);
    float s0, s1, s2, s3;
    {
        float v0 = sspf(d0 + bias1[c0]), v1 = sspf(d1 + bias1[c0 + 1]);
        float v2 = sspf(d2 + bias1[c0]), v3 = sspf(d3 + bias1[c0 + 1]);
        int gr0 = (b * 128 + it * 16 + row0) * 128 + c0;
        int gr1 = (b * 128 + it * 16 + row1) * 128 + c0;
        float2 t0 = *reinterpret_cast<float2*>(g_ysum + gr0);
        float2 t1 = *reinterpret_cast<float2*>(g_ysum + gr1);
        s0 = t0.x + v0; s1 = t0.y + v1; s2 = t1.x + v2; s3 = t1.y + v3;
        __syncthreads();
        if (mode != 2) {
            *reinterpret_cast<float2*>(g_ysum + gr0) = make_float2(s0, s1);
            *reinterpret_cast<float2*>(g_ysum + gr1) = make_float2(s2, s3);
            hilo_store(y2h, y2l, row0, c0, v0, v1);
            hilo_store(y2h, y2l, row1, c0, v2, v3);
        } else {
            hilo_store(y2h, y2l, row0, c0, s0, s1);   // A = final ysum
            hilo_store(y2h, y2l, row1, c0, s2, s3);
        }
    }
    __syncthreads();

    if (mode != 2) {
        d0 = d1 = d2 = d3 = 0.f;
        split_gemm(d0, d1, d2, d3, y2h, y2l, g_comboT_h, g_comboT_l, gr, ct, nc);
        int gr0 = (b * 128 + it * 16 + row0) * 128 + c0;
        int gr1 = (b * 128 + it * 16 + row1) * 128 + c0;
        float2 fi0 = *reinterpret_cast<const float2*>(f_in + gr0);
        float2 fi1 = *reinterpret_cast<const float2*>(f_in + gr1);
        float fb0 = fb_s[c0], fb1 = fb_s[c0 + 1];
        float o0 = fi0.x + fb0 + d0, o1 = fi0.y + fb1 + d1;
        float o2 = fi1.x + fb0 + d2, o3 = fi1.y + fb1 + d3;
        *reinterpret_cast<float2*>(f_out + gr0) = make_float2(o0, o1);
        *reinterpret_cast<float2*>(f_out + gr1) = make_float2(o2, o3);
        __half2 q01 = __floats2half2_rn(o0, o1);
        __half2 q23 = __floats2half2_rn(o2, o3);
        *reinterpret_cast<unsigned*>(fh_out + gr0) = *reinterpret_cast<unsigned*>(&q01);
        *reinterpret_cast<unsigned*>(fh_out + gr1) = *reinterpret_cast<unsigned*>(&q23);
        return;
    }

    // ---- mode 2: readout ----
    d0 = d1 = d2 = d3 = 0.f;
    split_gemm(d0, d1, d2, d3, y2h, y2l, g_woutT_h, g_woutT_l, gr, ct, nc);
    {
        int gr0 = (b * 128 + it * 16 + row0) * 128 + c0;
        int gr1 = (b * 128 + it * 16 + row1) * 128 + c0;
        float2 x0a = *reinterpret_cast<const float2*>(g_x + gr0);
        float2 x0b = *reinterpret_cast<const float2*>(g_x + gr1);
        float bo0 = 3.0f * fb_s[c0], bo1 = 3.0f * fb_s[c0 + 1];
        hilo_store(yh, yl, row0, c0, x0a.x + d0 + bo0, x0a.y + d1 + bo1);
        hilo_store(yh, yl, row1, c0, x0b.x + d2 + bo0, x0b.y + d3 + bo1);
    }
    __syncthreads();

    d0 = d1 = d2 = d3 = 0.f;
    split_gemm(d0, d1, d2, d3, yh, yl, g_aw1T_h, g_aw1T_l, gr, ct, nc);
    {
        float t0 = sspf(d0 + baw1[c0]), t1 = sspf(d1 + baw1[c0 + 1]);
        float t2 = sspf(d2 + baw1[c0]), t3 = sspf(d3 + baw1[c0 + 1]);
        float w0 = w2ro[c0], w1 = w2ro[c0 + 1];
        atomicAdd(&red[row0], t0 * w0 + t1 * w1);
        atomicAdd(&red[row1], t2 * w0 + t3 * w1);
    }
    __syncthreads();
    if (tid < 16)
        out[b * 128 + it * 16 + tid] = red[tid] + b_aw2[0];
}

extern "C" void kernel_launch(void* const* d_in, const int* in_sizes, int n_in,
                              void* d_out, int out_size)
{
    const int*   z       = (const int*)  d_in[0];
    const float* r       = (const float*)d_in[1];
    const float* emb     = (const float*)d_in[2];
    const float* w_in2f  = (const float*)d_in[3];
    const float* w_f1    = (const float*)d_in[4];
    const float* b_f1    = (const float*)d_in[5];
    const float* w_f2    = (const float*)d_in[6];
    const float* b_f2    = (const float*)d_in[7];
    const float* w_f2out = (const float*)d_in[8];
    const float* b_f2out = (const float*)d_in[9];
    const float* w_out   = (const float*)d_in[10];
    const float* b_out   = (const float*)d_in[11];
    const float* w_aw1   = (const float*)d_in[12];
    const float* b_aw1   = (const float*)d_in[13];
    const float* w_aw2   = (const float*)d_in[14];
    const float* b_aw2   = (const float*)d_in[15];
    float* out = (float*)d_out;

    cudaFuncSetAttribute(k_init, cudaFuncAttributeMaxDynamicSharedMemorySize, 73728);

    k_init<<<821, 256, 73728>>>(z, emb, w_in2f, w_out, b_out, w_f2out, w_aw1, r,
                                w_f1, b_f1, w_f2, b_f2);
    for (int it = 0; it < 3; it++) {
        k_gather<<<dim3(16, 32), 256>>>(it & 1);
        k_epi<<<dim3(8, 32), 512>>>(b_f2out, b_out, b_aw1, w_aw2, b_aw2, out, it);
    }
}

// round 17
// speedup vs baseline: 1.1983x; 1.0834x over previous
#include <cuda_runtime.h>
#include <cuda_fp16.h>

#define TC 8192
#define TF 65536
#define D_MAX 36.0f
#define NGAUSS 300

__device__ __align__(16) uint2  g_tabn[TF * 32];        // fine fp16 nearest table (16 MB)
__device__ __align__(16) float  g_x[4096 * 128];
__device__ __align__(16) float  g_fA[4096 * 128];
__device__ __align__(16) float  g_fB[4096 * 128];
__device__ __align__(16) __half g_fhA[4096 * 128];      // fp16 f mirrors for gather
__device__ __align__(16) __half g_fhB[4096 * 128];
__device__ __align__(16) float  g_yA[4096 * 128];       // partial gather sums (j 0..63)
__device__ __align__(16) float  g_yB[4096 * 128];       // partial gather sums (j 64..127)
__device__ __align__(16) float  g_ysum[4096 * 128];
__device__ __align__(16) float  g_fbias[128];
__device__ __align__(16) unsigned short g_idx[32 * 128 * 128];  // table indices (1 MB)
__device__ __align__(16) __half g_wf2T_h[128 * 128];    // w_f2out^T hi/lo fp16 [n][k]
__device__ __align__(16) __half g_wf2T_l[128 * 128];
__device__ __align__(16) __half g_comboT_h[128 * 128];  // (w_out@w_in2f)^T hi/lo
__device__ __align__(16) __half g_comboT_l[128 * 128];
__device__ __align__(16) __half g_woutT_h[128 * 128];   // w_out^T hi/lo
__device__ __align__(16) __half g_woutT_l[128 * 128];
__device__ __align__(16) __half g_aw1T_h[128 * 128];    // w_aw1^T hi/lo
__device__ __align__(16) __half g_aw1T_l[128 * 128];

__device__ __forceinline__ float sspf(float x) {
    return fmaxf(x, 0.0f) + log1pf(__expf(-fabsf(x))) - 0.69314718055994531f;
}

__device__ __forceinline__ void mma16816(float& d0, float& d1, float& d2, float& d3,
                                         unsigned a0, unsigned a1, unsigned a2, unsigned a3,
                                         unsigned b0, unsigned b1)
{
    asm volatile(
        "mma.sync.aligned.m16n8k16.row.col.f32.f16.f16.f32 "
        "{%0,%1,%2,%3}, {%4,%5,%6,%7}, {%8,%9}, {%0,%1,%2,%3};\n"
        : "+f"(d0), "+f"(d1), "+f"(d2), "+f"(d3)
        : "r"(a0), "r"(a1), "r"(a2), "r"(a3), "r"(b0), "r"(b1));
}

#define YHS 136
// split-precision GEMM: B prefetched to registers (MLP~32), dual accumulator chains
__device__ __forceinline__ void split_gemm(float& d0, float& d1, float& d2, float& d3,
                                           const __half* Ah, const __half* Al,
                                           const __half* BTh, const __half* BTl,
                                           int gr, int ct, int nc)
{
    unsigned bh[16], bl[16];
#pragma unroll
    for (int ks = 0; ks < 8; ks++) {
        int kb = ks * 16 + ct * 2;
        bh[ks * 2]     = *reinterpret_cast<const unsigned*>(BTh + nc * 128 + kb);
        bh[ks * 2 + 1] = *reinterpret_cast<const unsigned*>(BTh + nc * 128 + kb + 8);
        bl[ks * 2]     = *reinterpret_cast<const unsigned*>(BTl + nc * 128 + kb);
        bl[ks * 2 + 1] = *reinterpret_cast<const unsigned*>(BTl + nc * 128 + kb + 8);
    }
    float e0 = 0.f, e1 = 0.f, e2 = 0.f, e3 = 0.f;
#pragma unroll
    for (int ks = 0; ks < 8; ks++) {
        int kb = ks * 16 + ct * 2;
        unsigned a0 = *reinterpret_cast<const unsigned*>(Ah + gr * YHS + kb);
        unsigned a1 = *reinterpret_cast<const unsigned*>(Ah + (gr + 8) * YHS + kb);
        unsigned a2 = *reinterpret_cast<const unsigned*>(Ah + gr * YHS + kb + 8);
        unsigned a3 = *reinterpret_cast<const unsigned*>(Ah + (gr + 8) * YHS + kb + 8);
        unsigned l0 = *reinterpret_cast<const unsigned*>(Al + gr * YHS + kb);
        unsigned l1 = *reinterpret_cast<const unsigned*>(Al + (gr + 8) * YHS + kb);
        unsigned l2 = *reinterpret_cast<const unsigned*>(Al + gr * YHS + kb + 8);
        unsigned l3 = *reinterpret_cast<const unsigned*>(Al + (gr + 8) * YHS + kb + 8);
        if (ks & 1) {
            mma16816(d0, d1, d2, d3, a0, a1, a2, a3, bh[ks * 2], bh[ks * 2 + 1]);
            mma16816(d0, d1, d2, d3, l0, l1, l2, l3, bh[ks * 2], bh[ks * 2 + 1]);
            mma16816(d0, d1, d2, d3, a0, a1, a2, a3, bl[ks * 2], bl[ks * 2 + 1]);
        } else {
            mma16816(e0, e1, e2, e3, a0, a1, a2, a3, bh[ks * 2], bh[ks * 2 + 1]);
            mma16816(e0, e1, e2, e3, l0, l1, l2, l3, bh[ks * 2], bh[ks * 2 + 1]);
            mma16816(e0, e1, e2, e3, a0, a1, a2, a3, bl[ks * 2], bl[ks * 2 + 1]);
        }
    }
    d0 += e0; d1 += e1; d2 += e2; d3 += e3;
}

__device__ __forceinline__ void hilo_store(__half* H, __half* L, int row, int col,
                                           float v0, float v1)
{
    __half2 h = __floats2half2_rn(v0, v1);
    float2 q = __half22float2(h);
    __half2 l = __floats2half2_rn(v0 - q.x, v1 - q.y);
    *reinterpret_cast<unsigned*>(H + row * YHS + col) = *reinterpret_cast<unsigned*>(&h);
    *reinterpret_cast<unsigned*>(L + row * YHS + col) = *reinterpret_cast<unsigned*>(&l);
}

// ---- merged init: blocks 0-511 = table build; 512-820 = setup roles ----
__global__ void k_init(const int* __restrict__ z, const float* __restrict__ emb,
                       const float* __restrict__ w_in2f, const float* __restrict__ w_out,
                       const float* __restrict__ b_out, const float* __restrict__ w_f2out,
                       const float* __restrict__ w_aw1, const float* __restrict__ r,
                       const float* __restrict__ w1, const float* __restrict__ b1,
                       const float* __restrict__ w2, const float* __restrict__ b2)
{
    extern __shared__ float sm[];
    const int bx = blockIdx.x, tid = threadIdx.x;

    if (bx < 512) {
        float* w1s   = sm;                  // 32*128
        float* rbf_s = sm + 4096;           // 17*32
        float* As    = rbf_s + 544;         // 17*128
        const float hc = D_MAX / (float)TC;
        const float dc = 30.0f / 299.0f;
        const int t0c = bx * 16;
        const int tg = tid >> 7, h = tid & 127, T0 = tg * 8;

        float dmin = (float)t0c * hc, dmax = (float)(t0c + 16) * hc;
        int glo = (int)floorf((dmin - 1.4f) / dc); if (glo < 0) glo = 0;
        int ghi = (int)ceilf((dmax + 1.4f) / dc);  if (ghi > NGAUSS - 1) ghi = NGAUSS - 1;
        int ng = ghi - glo + 1; if (ng < 0) ng = 0; if (ng > 32) ng = 32;

        for (int idx = tid; idx < ng * 128; idx += 256) w1s[idx] = w1[glo * 128 + idx];
        for (int idx = tid; idx < 17 * ng; idx += 256) {
            int t = idx / ng, g = idx % ng;
            int tc = min(t0c + t, TC - 1);
            float u = (float)tc * hc - (float)(glo + g) * dc;
            rbf_s[t * 32 + g] = __expf(-10.0f * u * u);
        }
        __syncthreads();

        float acc[9];
#pragma unroll
        for (int t = 0; t < 9; t++) acc[t] = 0.0f;
        for (int g = 0; g < ng; g++) {
            float w = w1s[g * 128 + h];
#pragma unroll
            for (int t = 0; t < 9; t++) acc[t] += rbf_s[(T0 + t) * 32 + g] * w;
        }
        float bb = b1[h];
#pragma unroll
        for (int t = 0; t < 9; t++)
            if (tg == 0 || t > 0) As[(T0 + t) * 128 + h] = sspf(acc[t] + bb);
        __syncthreads();

#pragma unroll
        for (int t = 0; t < 9; t++) acc[t] = 0.0f;
        for (int k = 0; k < 128; k++) {
            float w = __ldg(&w2[k * 128 + h]);
#pragma unroll
            for (int t = 0; t < 9; t++) acc[t] += As[(T0 + t) * 128 + k] * w;
        }
        float b2v = b2[h];
        __syncthreads();
#pragma unroll
        for (int t = 0; t < 9; t++)
            if (tg == 0 || t > 0) As[(T0 + t) * 128 + h] = acc[t] + b2v;
        __syncthreads();

        for (int task = tid; task < 4096; task += 256) {
            int rho = task >> 5, h4 = task & 31;
            int u = rho >> 3;
            float fr = (float)(rho & 7) * 0.125f;
            float4 a = *reinterpret_cast<const float4*>(As + u * 128 + h4 * 4);
            float4 b = *reinterpret_cast<const float4*>(As + (u + 1) * 128 + h4 * 4);
            __half2 h01 = __floats2half2_rn(a.x + fr * (b.x - a.x), a.y + fr * (b.y - a.y));
            __half2 h23 = __floats2half2_rn(a.z + fr * (b.z - a.z), a.w + fr * (b.w - a.w));
            uint2 o;
            o.x = *reinterpret_cast<unsigned*>(&h01);
            o.y = *reinterpret_cast<unsigned*>(&h23);
            g_tabn[(bx * 128 + rho) * 32 + h4] = o;
        }
        return;
    }

    const int sx = bx - 512;
    float* ws = sm;            // [128][128]
    float* xs = sm + 16384;    // [16][128]

    if (sx >= 277) {           // distance -> table index, one block per batch
        float* rs = sm;
        const int b = sx - 277;
        if (tid < 128) {
            const float* rp = r + (b * 128 + tid) * 3;
            rs[tid] = rp[0]; rs[128 + tid] = rp[1]; rs[256 + tid] = rp[2];
        }
        __syncthreads();
        const float inv_h = (float)TF / D_MAX;
        for (int task = tid; task < 16384; task += 256) {
            int i = task >> 7, j = task & 127;
            float dx = rs[i] - rs[j], dy = rs[128 + i] - rs[128 + j], dz = rs[256 + i] - rs[256 + j];
            float d = sqrtf(dx * dx + dy * dy + dz * dz + 1e-12f);
            g_idx[b * 16384 + task] =
                (unsigned short)fminf(d * inv_h + 0.5f, (float)(TF - 1));
        }
        return;
    }
    if (sx >= 265) {
        const float* src; __half *dh, *dl;
        int role = (sx - 265) >> 2, base = ((sx - 265) & 3) * 4096;
        if (role == 0)      { src = w_f2out; dh = g_wf2T_h;  dl = g_wf2T_l; }
        else if (role == 1) { src = w_out;   dh = g_woutT_h; dl = g_woutT_l; }
        else                { src = w_aw1;   dh = g_aw1T_h;  dl = g_aw1T_l; }
        for (int e = base + tid; e < base + 4096; e += 256) {
            int n = e >> 7, k = e & 127;
            float v = src[k * 128 + n];
            __half hh = __float2half_rn(v);
            dh[e] = hh;
            dl[e] = __float2half_rn(v - __half2float(hh));
        }
        return;
    }

    for (int idx = tid; idx < 16384; idx += 256) ws[idx] = w_in2f[idx];
    if (sx < 256) {
        int r0 = sx * 16;
        for (int idx = tid; idx < 2048; idx += 256) {
            int i = idx >> 7, h = idx & 127;
            int zi = z[r0 + i];
            float v = emb[zi * 128 + h];
            xs[idx] = v;
            g_x[r0 * 128 + idx] = v;
            g_ysum[r0 * 128 + idx] = 0.0f;
        }
    } else if (sx < 264) {
        int r0 = (sx - 256) * 16;
        for (int idx = tid; idx < 2048; idx += 256) xs[idx] = w_out[r0 * 128 + idx];
    }
    __syncthreads();

    if (sx == 264) {
        if (tid < 128) {
            float s = 0.0f;
            for (int m = 0; m < 128; m++) s += __ldg(&b_out[m]) * ws[m * 128 + tid];
            g_fbias[tid] = s;
        }
        return;
    }
    const int rg = tid >> 5, hg = tid & 31;
    float a[2][4];
#pragma unroll
    for (int rr = 0; rr < 2; rr++)
#pragma unroll
        for (int c = 0; c < 4; c++) a[rr][c] = 0.0f;
    for (int k = 0; k < 128; k++) {
        float4 wb = *reinterpret_cast<const float4*>(ws + k * 128 + hg * 4);
        float y0 = xs[(rg * 2) * 128 + k], y1 = xs[(rg * 2 + 1) * 128 + k];
        a[0][0] += y0 * wb.x; a[0][1] += y0 * wb.y; a[0][2] += y0 * wb.z; a[0][3] += y0 * wb.w;
        a[1][0] += y1 * wb.x; a[1][1] += y1 * wb.y; a[1][2] += y1 * wb.z; a[1][3] += y1 * wb.w;
    }
    if (sx < 256) {
#pragma unroll
        for (int rr = 0; rr < 2; rr++) {
            int row = sx * 16 + rg * 2 + rr;
            *reinterpret_cast<float4*>(g_fA + row * 128 + hg * 4) =
                make_float4(a[rr][0], a[rr][1], a[rr][2], a[rr][3]);
            __half2 h01 = __floats2half2_rn(a[rr][0], a[rr][1]);
            __half2 h23 = __floats2half2_rn(a[rr][2], a[rr][3]);
            uint2 hv;
            hv.x = *reinterpret_cast<unsigned*>(&h01);
            hv.y = *reinterpret_cast<unsigned*>(&h23);
            *reinterpret_cast<uint2*>(g_fhA + row * 128 + hg * 4) = hv;
        }
    } else {
        __syncthreads();
#pragma unroll
        for (int rr = 0; rr < 2; rr++)
#pragma unroll
            for (int c = 0; c < 4; c++)
                xs[(rg * 2 + rr) * 128 + hg * 4 + c] = a[rr][c];
        __syncthreads();
        int r0 = (sx - 256) * 16;
        for (int e = tid; e < 2048; e += 256) {
            int n = e >> 4, q = e & 15;
            float v = xs[q * 128 + n];
            __half hh = __float2half_rn(v);
            g_comboT_h[n * 128 + r0 + q] = hh;
            g_comboT_l[n * 128 + r0 + q] = __float2half_rn(v - __half2float(hh));
        }
    }
}

// ---- gather (j-split): block (x = it*2+half, b). 8 rows x 64 j. grid (32,32) x 256 ----
__global__ void __launch_bounds__(256) k_gather(int flag)
{
    __shared__ __align__(16) __half f_s[64 * 128];    // 16 KB (j-half of f)
    __shared__ unsigned idx_s[8 * 32];                // 1 KB
    const int bx = blockIdx.x, b = blockIdx.y, tid = threadIdx.x;
    const int it = bx >> 1, half = bx & 1;
    const __half* fh = (flag ? g_fhB : g_fhA) + b * 16384 + half * 64 * 128;

    {
        // idx rows it*8..+7, j-range half*64..+63 (32 uints per row)
        const unsigned* gi = reinterpret_cast<const unsigned*>(g_idx + (b * 128 + it * 8) * 128);
        int rr = tid >> 5, q = tid & 31;
        idx_s[tid] = gi[rr * 64 + half * 32 + q];
    }
    for (int i2 = tid; i2 < 1024; i2 += 256)
        reinterpret_cast<uint4*>(f_s)[i2] = reinterpret_cast<const uint4*>(fh)[i2];
    __syncthreads();

    const int w = tid >> 5, lane = tid & 31;
    const unsigned* ip = idx_s + w * 32;
    float a0 = 0.f, a1 = 0.f, a2 = 0.f, a3 = 0.f;
#pragma unroll 8
    for (int j2 = 0; j2 < 32; j2++) {
        unsigned pr = ip[j2];
        unsigned t0 = pr & 0xFFFFu, t1 = pr >> 16;
        uint2 u0 = g_tabn[t0 * 32 + lane];
        uint2 u1 = g_tabn[t1 * 32 + lane];
        uint2 fv0 = *reinterpret_cast<const uint2*>(f_s + (j2 * 2) * 128 + lane * 4);
        uint2 fv1 = *reinterpret_cast<const uint2*>(f_s + (j2 * 2 + 1) * 128 + lane * 4);
        {
            __half2 w01 = *reinterpret_cast<__half2*>(&u0.x);
            __half2 w23 = *reinterpret_cast<__half2*>(&u0.y);
            __half2 f01 = *reinterpret_cast<__half2*>(&fv0.x);
            __half2 f23 = *reinterpret_cast<__half2*>(&fv0.y);
            float2 pw0 = __half22float2(w01), pw1 = __half22float2(w23);
            float2 pf0 = __half22float2(f01), pf1 = __half22float2(f23);
            a0 = fmaf(pw0.x, pf0.x, a0);
            a1 = fmaf(pw0.y, pf0.y, a1);
            a2 = fmaf(pw1.x, pf1.x, a2);
            a3 = fmaf(pw1.y, pf1.y, a3);
        }
        {
            __half2 w01 = *reinterpret_cast<__half2*>(&u1.x);
            __half2 w23 = *reinterpret_cast<__half2*>(&u1.y);
            __half2 f01 = *reinterpret_cast<__half2*>(&fv1.x);
            __half2 f23 = *reinterpret_cast<__half2*>(&fv1.y);
            float2 pw0 = __half22float2(w01), pw1 = __half22float2(w23);
            float2 pf0 = __half22float2(f01), pf1 = __half22float2(f23);
            a0 = fmaf(pw0.x, pf0.x, a0);
            a1 = fmaf(pw0.y, pf0.y, a1);
            a2 = fmaf(pw1.x, pf1.x, a2);
            a3 = fmaf(pw1.y, pf1.y, a3);
        }
    }
    int i = it * 8 + w;
    float* yp = half ? g_yB : g_yA;
    *reinterpret_cast<float4*>(yp + (b * 128 + i) * 128 + lane * 4) =
        make_float4(a0, a1, a2, a3);
}

// ---- epilogue (split-mma, B prefetched) + mode-2 readout. grid (8,32) x 512 ----
__global__ void __launch_bounds__(512)
k_epi(const float* __restrict__ b_f2out, const float* __restrict__ b_out,
      const float* __restrict__ b_aw1, const float* __restrict__ w_aw2,
      const float* __restrict__ b_aw2, float* __restrict__ out, int mode)
{
    __shared__ __align__(16) __half yh[16 * YHS], yl[16 * YHS];
    __shared__ __align__(16) __half y2h[16 * YHS], y2l[16 * YHS];
    __shared__ float bias1[128], fb_s[128], baw1[128], w2ro[128], red[16];
    const int it = blockIdx.x, b = blockIdx.y, tid = threadIdx.x;
    const int flag = (mode == 1) ? 1 : 0;
    const float* f_in  = flag ? g_fB : g_fA;
    float*       f_out = flag ? g_fA : g_fB;
    __half*      fh_out = flag ? g_fhA : g_fhB;

    if (tid < 128) bias1[tid] = b_f2out[tid];
    else if (tid < 256) fb_s[tid - 128] = (mode == 2) ? b_out[tid - 128] : g_fbias[tid - 128];
    else if (tid < 384) baw1[tid - 256] = b_aw1[tid - 256];
    else w2ro[tid - 384] = w_aw2[tid - 384];
    if (tid < 16) red[tid] = 0.0f;
    {
        int row = tid >> 5, h4 = tid & 31;
        int off = (b * 128 + it * 16 + row) * 128 + h4 * 4;
        float4 ya = *reinterpret_cast<const float4*>(g_yA + off);
        float4 yb = *reinterpret_cast<const float4*>(g_yB + off);
        hilo_store(yh, yl, row, h4 * 4, ya.x + yb.x, ya.y + yb.y);
        hilo_store(yh, yl, row, h4 * 4 + 2, ya.z + yb.z, ya.w + yb.w);
    }
    __syncthreads();

    const int w = tid >> 5, lane = tid & 31;
    const int gr = lane >> 2, ct = lane & 3, n0 = w * 8;
    const int nc = n0 + gr;
    const int c0 = n0 + ct * 2;
    const int row0 = gr, row1 = gr + 8;
    float d0 = 0.f, d1 = 0.f, d2 = 0.f, d3 = 0.f;
    split_gemm(d0, d1, d2, d3, yh, yl, g_wf2T_h, g_wf2T_l, gr, ct, nc);
    float s0, s1, s2, s3;
    {
        float v0 = sspf(d0 + bias1[c0]), v1 = sspf(d1 + bias1[c0 + 1]);
        float v2 = sspf(d2 + bias1[c0]), v3 = sspf(d3 + bias1[c0 + 1]);
        int gr0 = (b * 128 + it * 16 + row0) * 128 + c0;
        int gr1 = (b * 128 + it * 16 + row1) * 128 + c0;
        float2 t0 = *reinterpret_cast<float2*>(g_ysum + gr0);
        float2 t1 = *reinterpret_cast<float2*>(g_ysum + gr1);
        s0 = t0.x + v0; s1 = t0.y + v1; s2 = t1.x + v2; s3 = t1.y + v3;
        __syncthreads();
        if (mode != 2) {
            *reinterpret_cast<float2*>(g_ysum + gr0) = make_float2(s0, s1);
            *reinterpret_cast<float2*>(g_ysum + gr1) = make_float2(s2, s3);
            hilo_store(y2h, y2l, row0, c0, v0, v1);
            hilo_store(y2h, y2l, row1, c0, v2, v3);
        } else {
            hilo_store(y2h, y2l, row0, c0, s0, s1);   // A = final ysum
            hilo_store(y2h, y2l, row1, c0, s2, s3);
        }
    }
    __syncthreads();

    if (mode != 2) {
        d0 = d1 = d2 = d3 = 0.f;
        split_gemm(d0, d1, d2, d3, y2h, y2l, g_comboT_h, g_comboT_l, gr, ct, nc);
        int gr0 = (b * 128 + it * 16 + row0) * 128 + c0;
        int gr1 = (b * 128 + it * 16 + row1) * 128 + c0;
        float2 fi0 = *reinterpret_cast<const float2*>(f_in + gr0);
        float2 fi1 = *reinterpret_cast<const float2*>(f_in + gr1);
        float fb0 = fb_s[c0], fb1 = fb_s[c0 + 1];
        float o0 = fi0.x + fb0 + d0, o1 = fi0.y + fb1 + d1;
        float o2 = fi1.x + fb0 + d2, o3 = fi1.y + fb1 + d3;
        *reinterpret_cast<float2*>(f_out + gr0) = make_float2(o0, o1);
        *reinterpret_cast<float2*>(f_out + gr1) = make_float2(o2, o3);
        __half2 q01 = __floats2half2_rn(o0, o1);
        __half2 q23 = __floats2half2_rn(o2, o3);
        *reinterpret_cast<unsigned*>(fh_out + gr0) = *reinterpret_cast<unsigned*>(&q01);
        *reinterpret_cast<unsigned*>(fh_out + gr1) = *reinterpret_cast<unsigned*>(&q23);
        return;
    }

    // ---- mode 2: readout ----
    d0 = d1 = d2 = d3 = 0.f;
    split_gemm(d0, d1, d2, d3, y2h, y2l, g_woutT_h, g_woutT_l, gr, ct, nc);
    {
        int gr0 = (b * 128 + it * 16 + row0) * 128 + c0;
        int gr1 = (b * 128 + it * 16 + row1) * 128 + c0;
        float2 x0a = *reinterpret_cast<const float2*>(g_x + gr0);
        float2 x0b = *reinterpret_cast<const float2*>(g_x + gr1);
        float bo0 = 3.0f * fb_s[c0], bo1 = 3.0f * fb_s[c0 + 1];
        hilo_store(yh, yl, row0, c0, x0a.x + d0 + bo0, x0a.y + d1 + bo1);
        hilo_store(yh, yl, row1, c0, x0b.x + d2 + bo0, x0b.y + d3 + bo1);
    }
    __syncthreads();

    d0 = d1 = d2 = d3 = 0.f;
    split_gemm(d0, d1, d2, d3, yh, yl, g_aw1T_h, g_aw1T_l, gr, ct, nc);
    {
        float t0 = sspf(d0 + baw1[c0]), t1 = sspf(d1 + baw1[c0 + 1]);
        float t2 = sspf(d2 + baw1[c0]), t3 = sspf(d3 + baw1[c0 + 1]);
        float w0 = w2ro[c0], w1 = w2ro[c0 + 1];
        atomicAdd(&red[row0], t0 * w0 + t1 * w1);
        atomicAdd(&red[row1], t2 * w0 + t3 * w1);
    }
    __syncthreads();
    if (tid < 16)
        out[b * 128 + it * 16 + tid] = red[tid] + b_aw2[0];
}

extern "C" void kernel_launch(void* const* d_in, const int* in_sizes, int n_in,
                              void* d_out, int out_size)
{
    const int*   z       = (const int*)  d_in[0];
    const float* r       = (const float*)d_in[1];
    const float* emb     = (const float*)d_in[2];
    const float* w_in2f  = (const float*)d_in[3];
    const float* w_f1    = (const float*)d_in[4];
    const float* b_f1    = (const float*)d_in[5];
    const float* w_f2    = (const float*)d_in[6];
    const float* b_f2    = (const float*)d_in[7];
    const float* w_f2out = (const float*)d_in[8];
    const float* b_f2out = (const float*)d_in[9];
    const float* w_out   = (const float*)d_in[10];
    const float* b_out   = (const float*)d_in[11];
    const float* w_aw1   = (const float*)d_in[12];
    const float* b_aw1   = (const float*)d_in[13];
    const float* w_aw2   = (const float*)d_in[14];
    const float* b_aw2   = (const float*)d_in[15];
    float* out = (float*)d_out;

    cudaFuncSetAttribute(k_init, cudaFuncAttributeMaxDynamicSharedMemorySize, 73728);

    k_init<<<821, 256, 73728>>>(z, emb, w_in2f, w_out, b_out, w_f2out, w_aw1, r,
                                w_f1, b_f1, w_f2, b_f2);
    for (int it = 0; it < 3; it++) {
        k_gather<<<dim3(32, 32), 256>>>(it & 1);
        k_epi<<<dim3(8, 32), 512>>>(b_f2out, b_out, b_aw1, w_aw2, b_aw2, out, it);
    }
}